// round 4
// baseline (speedup 1.0000x reference)
#include <cuda_runtime.h>
#include <cuda_bf16.h>
#include <math.h>
#include <stdint.h>

// Problem constants
#define LL   8
#define DD   512
#define HH   8
#define DHH  64
#define SS   64
#define VV   66
#define BB   256
#define MM   (BB * SS)      // 16384 token rows
#define DFF  (4 * DD)       // 2048
#define K3D  (3 * DD)       // 1536
#define K3F  (3 * DFF)      // 6144

// ---------------- scratch (static device allocations; no cudaMalloc) -------
__device__ float g_x[(size_t)MM * DD];
__device__ float g_h[(size_t)MM * DD];
__device__ float g_qkv[(size_t)MM * K3D];           // fp32 qkv [M, 1536]
__device__ __nv_bfloat16 g_hA[(size_t)MM * K3D];    // triple-bf16 LN out [hi|lo|hi]
__device__ __nv_bfloat16 g_oA[(size_t)MM * K3D];    // triple-bf16 attn out
__device__ __nv_bfloat16 g_hidA[(size_t)MM * K3F];  // triple-bf16 gelu out
__device__ float g_logits[(size_t)MM * VV];
__device__ float g_loss;

// triple-bf16 transposed weights [N rows][3K cols], layout [hi|hi|lo]
__device__ __nv_bfloat16 g_Wqkv[(size_t)LL * K3D * K3D];
__device__ __nv_bfloat16 g_WoT [(size_t)LL * DD * K3D];
__device__ __nv_bfloat16 g_W1T [(size_t)LL * DFF * K3D];
__device__ __nv_bfloat16 g_W2T [(size_t)LL * DD * K3F];

// ============================ PTX helpers ===================================
__device__ __forceinline__ uint32_t smem_u32(const void* p) {
    uint32_t a;
    asm("{ .reg .u64 t; cvta.to.shared.u64 t, %1; cvt.u32.u64 %0, t; }"
        : "=r"(a) : "l"(p));
    return a;
}
__device__ __forceinline__ void cp16(uint32_t s, const void* g) {
    asm volatile("cp.async.cg.shared.global [%0], [%1], 16;" :: "r"(s), "l"(g));
}
__device__ __forceinline__ void cp_commit() {
    asm volatile("cp.async.commit_group;" ::: "memory");
}
template<int N>
__device__ __forceinline__ void cp_wait() {
    asm volatile("cp.async.wait_group %0;" :: "n"(N) : "memory");
}
__device__ __forceinline__ void ldsm4(uint32_t* r, uint32_t addr) {
    asm volatile("ldmatrix.sync.aligned.m8n8.x4.shared.b16 {%0,%1,%2,%3}, [%4];"
        : "=r"(r[0]), "=r"(r[1]), "=r"(r[2]), "=r"(r[3]) : "r"(addr));
}
__device__ __forceinline__ void mma16816(float* d, const uint32_t* a, uint32_t b0, uint32_t b1) {
    asm volatile(
        "mma.sync.aligned.m16n8k16.row.col.f32.bf16.bf16.f32 "
        "{%0,%1,%2,%3}, {%4,%5,%6,%7}, {%8,%9}, {%0,%1,%2,%3};"
        : "+f"(d[0]), "+f"(d[1]), "+f"(d[2]), "+f"(d[3])
        : "r"(a[0]), "r"(a[1]), "r"(a[2]), "r"(a[3]), "r"(b0), "r"(b1));
}

// ============================ HMMA GEMM =====================================
// C[M,N] = A'[M,K3] @ B'[N,K3]^T, triple-bf16 K-major.
// CTA tile 128x256 (BM x BN), BK=64, 3-stage cp.async pipeline.
// 8 warps in 2m x 4n grid, each warp 64x64 (4 m16 x 8 n8 MMA tiles).
// EPI 0: C fp32
// EPI 1: C = acc + bias + res   (fp32, res==C aliasing ok)
// EPI 2: C3 = triple-bf16(gelu(acc + bias)), activation layout [hi|lo|hi]
#define STG       3
#define STG_BYTES 49152u   // A 16KB + B 32KB per stage

template<int EPI>
__global__ void __launch_bounds__(256, 1)
gemm_mma(const __nv_bfloat16* __restrict__ A, int lda,
         const __nv_bfloat16* __restrict__ B, int ldb,
         int K3,
         float* __restrict__ C, int ldc,
         const float* __restrict__ bias,
         float* __restrict__ res,
         __nv_bfloat16* __restrict__ C3, int kseg)
{
    extern __shared__ char smem[];
    const int t    = threadIdx.x;
    const int wid  = t >> 5, lane = t & 31;
    const int brow = blockIdx.y * 128;
    const int bcol = blockIdx.x * 256;
    const int wm   = (wid & 1) * 64;
    const int wn   = (wid >> 1) * 64;

    uint32_t sbase = smem_u32(smem);

    float acc[4][8][4];
    #pragma unroll
    for (int i = 0; i < 4; i++)
        #pragma unroll
        for (int j = 0; j < 8; j++)
            #pragma unroll
            for (int e = 0; e < 4; e++) acc[i][j][e] = 0.0f;

    // ---- stage loader: A 128x64 + B 256x64 bf16, SW128 swizzle -------------
    auto load_stage = [&](int s) {
        int buf = s % STG;
        int k0  = s << 6;
        uint32_t sa = sbase + buf * STG_BYTES;
        uint32_t sb = sa + 16384u;
        #pragma unroll
        for (int i = 0; i < 4; i++) {          // A: 1024 cp16
            int c   = t + (i << 8);
            int row = c >> 3;
            int c16 = c & 7;
            uint32_t off = (uint32_t)(row * 128 + c16 * 16);
            off ^= (off >> 3) & 0x70u;
            cp16(sa + off, A + (size_t)(brow + row) * lda + k0 + c16 * 8);
        }
        #pragma unroll
        for (int i = 0; i < 8; i++) {          // B: 2048 cp16
            int c   = t + (i << 8);
            int row = c >> 3;
            int c16 = c & 7;
            uint32_t off = (uint32_t)(row * 128 + c16 * 16);
            off ^= (off >> 3) & 0x70u;
            cp16(sb + off, B + (size_t)(bcol + row) * ldb + k0 + c16 * 8);
        }
        cp_commit();
    };

    const int S = K3 >> 6;

    const int lrow = ((lane >> 3) & 1) * 8 + (lane & 7);
    const int lkb  = (lane >> 4) * 16;

    load_stage(0);
    load_stage(1);

    for (int s = 0; s < S; s++) {
        int buf = s % STG;
        cp_wait<1>();
        __syncthreads();

        uint32_t sa = sbase + buf * STG_BYTES;
        uint32_t sb = sa + 16384u;

        #pragma unroll
        for (int kk = 0; kk < 4; kk++) {
            int kbyte = kk * 32 + lkb;

            uint32_t afr[4][4];
            #pragma unroll
            for (int mi = 0; mi < 4; mi++) {
                uint32_t off = (uint32_t)((wm + mi * 16 + lrow) * 128 + kbyte);
                off ^= (off >> 3) & 0x70u;
                ldsm4(afr[mi], sa + off);
            }
            uint32_t bfr[4][4];
            #pragma unroll
            for (int nj = 0; nj < 4; nj++) {
                uint32_t off = (uint32_t)((wn + nj * 16 + lrow) * 128 + kbyte);
                off ^= (off >> 3) & 0x70u;
                ldsm4(bfr[nj], sb + off);
            }
            #pragma unroll
            for (int mi = 0; mi < 4; mi++) {
                #pragma unroll
                for (int nj = 0; nj < 4; nj++) {
                    mma16816(acc[mi][2 * nj],     afr[mi], bfr[nj][0], bfr[nj][2]);
                    mma16816(acc[mi][2 * nj + 1], afr[mi], bfr[nj][1], bfr[nj][3]);
                }
            }
        }
        __syncthreads();
        if (s + 2 < S) load_stage(s + 2);
    }

    // ---- epilogue (register-resident mma layout) ----------------------------
    #pragma unroll
    for (int mi = 0; mi < 4; mi++) {
        #pragma unroll
        for (int ni = 0; ni < 8; ni++) {
            int r0 = brow + wm + mi * 16 + (lane >> 2);
            int c0 = bcol + wn + ni * 8 + ((lane & 3) << 1);
            #pragma unroll
            for (int half = 0; half < 2; half++) {
                int row = r0 + half * 8;
                float v0 = acc[mi][ni][half * 2];
                float v1 = acc[mi][ni][half * 2 + 1];
                if (EPI == 0) {
                    *(float2*)&C[(size_t)row * ldc + c0] = make_float2(v0, v1);
                } else if (EPI == 1) {
                    float2 r = *(const float2*)&res[(size_t)row * ldc + c0];
                    *(float2*)&C[(size_t)row * ldc + c0] =
                        make_float2(v0 + bias[c0] + r.x, v1 + bias[c0 + 1] + r.y);
                } else {
                    float a0 = v0 + bias[c0];
                    float a1 = v1 + bias[c0 + 1];
                    float g0 = 0.5f * a0 * (1.0f + erff(a0 * 0.70710678118654752f));
                    float g1 = 0.5f * a1 * (1.0f + erff(a1 * 0.70710678118654752f));
                    __nv_bfloat16 h0 = __float2bfloat16(g0);
                    __nv_bfloat16 l0 = __float2bfloat16(g0 - __bfloat162float(h0));
                    __nv_bfloat16 h1 = __float2bfloat16(g1);
                    __nv_bfloat16 l1 = __float2bfloat16(g1 - __bfloat162float(h1));
                    size_t ro = (size_t)row * (3 * kseg);
                    *(__nv_bfloat162*)&C3[ro + c0]            = __nv_bfloat162(h0, h1);
                    *(__nv_bfloat162*)&C3[ro + kseg + c0]     = __nv_bfloat162(l0, l1);
                    *(__nv_bfloat162*)&C3[ro + 2 * kseg + c0] = __nv_bfloat162(h0, h1);
                }
            }
        }
    }
}

// ============================ weight prep ===================================
// W[K,N] fp32 -> out[N][3K] bf16 triple [hi|hi|lo], tiled transpose
__global__ void __launch_bounds__(256) prep_w_kernel(
    const float* __restrict__ W, int K, int N, __nv_bfloat16* __restrict__ out)
{
    __shared__ float ts[32][33];
    int k0 = blockIdx.x * 32, n0 = blockIdx.y * 32;
    int tx = threadIdx.x, ty = threadIdx.y;   // 32 x 8
    #pragma unroll
    for (int i = 0; i < 32; i += 8)
        ts[ty + i][tx] = W[(size_t)(k0 + ty + i) * N + n0 + tx];
    __syncthreads();
    #pragma unroll
    for (int i = 0; i < 32; i += 8) {
        int n = n0 + ty + i, k = k0 + tx;
        float w = ts[tx][ty + i];
        __nv_bfloat16 hi = __float2bfloat16(w);
        __nv_bfloat16 lo = __float2bfloat16(w - __bfloat162float(hi));
        size_t ro = (size_t)n * (3 * K);
        out[ro + k]         = hi;
        out[ro + K + k]     = hi;
        out[ro + 2 * K + k] = lo;
    }
}

// ---------------- embedding + loss reset ------------------------------------
__global__ void __launch_bounds__(256) embed_kernel(
    const int* __restrict__ ids, const float* __restrict__ tok,
    const float* __restrict__ pos, float* __restrict__ x)
{
    int i = blockIdx.x * 256 + threadIdx.x;
    if (i == 0) g_loss = 0.0f;
    if (i >= MM * DD) return;
    int row = i / DD;
    int d   = i - row * DD;
    int s   = row % SS;
    x[i] = tok[(size_t)ids[row] * DD + d] + pos[(size_t)s * DD + d];
}

// ---------------- LayerNorm core (unbiased std, eps on std) -----------------
__device__ __forceinline__ void ln_stats(const float4& v, int t, float& mean, float& inv)
{
    float s  = v.x + v.y + v.z + v.w;
    float ss = v.x * v.x + v.y * v.y + v.z * v.z + v.w * v.w;
    #pragma unroll
    for (int o = 16; o; o >>= 1) {
        s  += __shfl_xor_sync(0xffffffffu, s,  o);
        ss += __shfl_xor_sync(0xffffffffu, ss, o);
    }
    __shared__ float sh[8];
    int wid = t >> 5, lane = t & 31;
    if (lane == 0) { sh[wid * 2] = s; sh[wid * 2 + 1] = ss; }
    __syncthreads();
    s  = sh[0] + sh[2] + sh[4] + sh[6];
    ss = sh[1] + sh[3] + sh[5] + sh[7];
    mean = s * (1.0f / DD);
    float var = (ss - s * mean) * (1.0f / (DD - 1));
    inv = 1.0f / (sqrtf(fmaxf(var, 0.0f)) + 1e-10f);
}

__global__ void __launch_bounds__(128) ln_kernel(
    const float* __restrict__ x, const float* __restrict__ g,
    const float* __restrict__ b, float* __restrict__ out)
{
    int row = blockIdx.x, t = threadIdx.x;
    float4 v = ((const float4*)(x + (size_t)row * DD))[t];
    float mean, inv;
    ln_stats(v, t, mean, inv);
    float4 gv = ((const float4*)g)[t], bv = ((const float4*)b)[t];
    float4 ov;
    ov.x = (v.x - mean) * inv * gv.x + bv.x;
    ov.y = (v.y - mean) * inv * gv.y + bv.y;
    ov.z = (v.z - mean) * inv * gv.z + bv.z;
    ov.w = (v.w - mean) * inv * gv.w + bv.w;
    ((float4*)(out + (size_t)row * DD))[t] = ov;
}

// LN -> triple bf16 [hi|lo|hi], row stride 1536
__global__ void __launch_bounds__(128) ln_triple_kernel(
    const float* __restrict__ x, const float* __restrict__ g,
    const float* __restrict__ b, __nv_bfloat16* __restrict__ out)
{
    int row = blockIdx.x, t = threadIdx.x;
    float4 v = ((const float4*)(x + (size_t)row * DD))[t];
    float mean, inv;
    ln_stats(v, t, mean, inv);
    float4 gv = ((const float4*)g)[t], bv = ((const float4*)b)[t];
    float o[4] = {
        (v.x - mean) * inv * gv.x + bv.x,
        (v.y - mean) * inv * gv.y + bv.y,
        (v.z - mean) * inv * gv.z + bv.z,
        (v.w - mean) * inv * gv.w + bv.w };
    size_t ro = (size_t)row * K3D + t * 4;
    #pragma unroll
    for (int j = 0; j < 4; j++) {
        __nv_bfloat16 hi = __float2bfloat16(o[j]);
        __nv_bfloat16 lo = __float2bfloat16(o[j] - __bfloat162float(hi));
        out[ro + j]            = hi;
        out[ro + DD + j]       = lo;
        out[ro + 2 * DD + j]   = hi;
    }
}

// ---------------- fused causal attention per (b,h) --------------------------
__global__ void __launch_bounds__(256) attn_kernel(
    const float* __restrict__ qkv, __nv_bfloat16* __restrict__ oA)
{
    int bh = blockIdx.x;
    int b  = bh >> 3;
    int h  = bh & 7;
    const float* qb = qkv + (size_t)b * SS * K3D + h * DHH;
    const float* kb = qb + DD;
    const float* vb = qb + 2 * DD;
    __nv_bfloat16* ob = oA + (size_t)b * SS * K3D + h * DHH;

    __shared__ float Ks[SS][DHH + 1];
    __shared__ float Vs[SS][DHH + 1];
    __shared__ float attn_s[8][SS];

    int tid = threadIdx.x;
    for (int i = tid; i < SS * DHH; i += 256) {
        int s = i >> 6, e = i & 63;
        Ks[s][e] = kb[(size_t)s * K3D + e];
        Vs[s][e] = vb[(size_t)s * K3D + e];
    }
    __syncthreads();

    int warp = tid >> 5, lane = tid & 31;
    const float scale = 0.044194173824159216f;  // 1/sqrt(512)

    for (int r = 0; r < 8; r++) {
        int s = warp * 8 + r;
        float q0 = qb[(size_t)s * K3D + lane];
        float q1 = qb[(size_t)s * K3D + lane + 32];

        float sc0 = 0.0f, sc1 = 0.0f;
        #pragma unroll
        for (int e = 0; e < 32; e++) {
            float qe = __shfl_sync(0xffffffffu, q0, e);
            sc0 = fmaf(qe, Ks[lane][e],      sc0);
            sc1 = fmaf(qe, Ks[lane + 32][e], sc1);
        }
        #pragma unroll
        for (int e = 0; e < 32; e++) {
            float qe = __shfl_sync(0xffffffffu, q1, e);
            sc0 = fmaf(qe, Ks[lane][e + 32],      sc0);
            sc1 = fmaf(qe, Ks[lane + 32][e + 32], sc1);
        }
        sc0 = (lane <= s)      ? sc0 * scale : -1e30f;
        sc1 = (lane + 32 <= s) ? sc1 * scale : -1e30f;

        float m = fmaxf(sc0, sc1);
        #pragma unroll
        for (int off = 16; off; off >>= 1)
            m = fmaxf(m, __shfl_xor_sync(0xffffffffu, m, off));
        float e0 = __expf(sc0 - m), e1 = __expf(sc1 - m);
        float sum = e0 + e1;
        #pragma unroll
        for (int off = 16; off; off >>= 1)
            sum += __shfl_xor_sync(0xffffffffu, sum, off);
        float invs = 1.0f / sum;
        attn_s[warp][lane]      = e0 * invs;
        attn_s[warp][lane + 32] = e1 * invs;
        __syncwarp();

        float o0 = 0.0f, o1 = 0.0f;
        #pragma unroll
        for (int tt = 0; tt < SS; tt++) {
            float a = attn_s[warp][tt];
            o0 = fmaf(a, Vs[tt][lane],      o0);
            o1 = fmaf(a, Vs[tt][lane + 32], o1);
        }
        size_t ro = (size_t)s * K3D;
        __nv_bfloat16 h0 = __float2bfloat16(o0);
        __nv_bfloat16 l0 = __float2bfloat16(o0 - __bfloat162float(h0));
        __nv_bfloat16 h1 = __float2bfloat16(o1);
        __nv_bfloat16 l1 = __float2bfloat16(o1 - __bfloat162float(h1));
        ob[ro + lane]               = h0;
        ob[ro + DD + lane]          = l0;
        ob[ro + 2 * DD + lane]      = h0;
        ob[ro + lane + 32]          = h1;
        ob[ro + DD + lane + 32]     = l1;
        ob[ro + 2 * DD + lane + 32] = h1;
        __syncwarp();
    }
}

// ---------------- unembed: logits = x @ Wu + bu -----------------------------
__global__ void __launch_bounds__(128) unembed_kernel(
    const float* __restrict__ x, const float* __restrict__ Wu,
    const float* __restrict__ bu, float* __restrict__ logits)
{
    __shared__ float xs[DD];
    int row = blockIdx.x;
    for (int i = threadIdx.x; i < DD; i += 128)
        xs[i] = x[(size_t)row * DD + i];
    __syncthreads();
    int n = threadIdx.x;
    if (n < VV) {
        float acc = bu[n];
        #pragma unroll 8
        for (int kk = 0; kk < DD; kk++)
            acc = fmaf(xs[kk], Wu[(size_t)kk * VV + n], acc);
        logits[(size_t)row * VV + n] = acc;
    }
}

// ---------------- cross-entropy loss ----------------------------------------
__global__ void __launch_bounds__(128) loss_kernel(
    const float* __restrict__ logits, const int* __restrict__ tgt)
{
    int warp = threadIdx.x >> 5, lane = threadIdx.x & 31;
    int row  = blockIdx.x * 4 + warp;
    const float* lr = logits + (size_t)row * VV;

    float l0 = lr[lane];
    float l1 = lr[lane + 32];
    float l2 = (lane + 64 < VV) ? lr[lane + 64] : -1e30f;

    float m = fmaxf(fmaxf(l0, l1), l2);
    #pragma unroll
    for (int off = 16; off; off >>= 1)
        m = fmaxf(m, __shfl_xor_sync(0xffffffffu, m, off));
    float sum = expf(l0 - m) + expf(l1 - m) + ((lane + 64 < VV) ? expf(l2 - m) : 0.0f);
    #pragma unroll
    for (int off = 16; off; off >>= 1)
        sum += __shfl_xor_sync(0xffffffffu, sum, off);

    if (lane == 0) {
        float lse = m + logf(sum);
        float lt  = lr[tgt[row]];
        atomicAdd(&g_loss, lse - lt);
    }
}

// ---------------- output assembly -------------------------------------------
__global__ void __launch_bounds__(256) copy_out_kernel(
    const float* __restrict__ lg, float* __restrict__ out, int n)
{
    int i = blockIdx.x * 256 + threadIdx.x;
    if (i < n) out[i] = lg[i];
}
__global__ void __launch_bounds__(128) write_loss_kernel(
    float* __restrict__ out, int lo, int hi)
{
    int i = lo + blockIdx.x * 128 + threadIdx.x;
    if (i < hi) out[i] = g_loss * (1.0f / (float)MM);
}

// ---------------- launcher ----------------------------------------------------
#define GSMEM (STG * 49152)

extern "C" void kernel_launch(void* const* d_in, const int* in_sizes, int n_in,
                              void* d_out, int out_size)
{
    const int*   ids  = (const int*)d_in[0];
    const int*   tgt  = (const int*)d_in[1];
    const float* tok  = (const float*)d_in[2];
    const float* pos  = (const float*)d_in[3];
    const float* Wq   = (const float*)d_in[4];
    const float* Wk   = (const float*)d_in[5];
    const float* Wv   = (const float*)d_in[6];
    const float* Wo   = (const float*)d_in[7];
    const float* bo   = (const float*)d_in[8];
    const float* W1   = (const float*)d_in[9];
    const float* b1   = (const float*)d_in[10];
    const float* W2   = (const float*)d_in[11];
    const float* b2   = (const float*)d_in[12];
    const float* ln1g = (const float*)d_in[13];
    const float* ln1b = (const float*)d_in[14];
    const float* ln2g = (const float*)d_in[15];
    const float* ln2b = (const float*)d_in[16];
    const float* lnfg = (const float*)d_in[17];
    const float* lnfb = (const float*)d_in[18];
    const float* Wu   = (const float*)d_in[19];
    const float* bu   = (const float*)d_in[20];
    float* out = (float*)d_out;

    float *x, *h, *qkv, *lg;
    __nv_bfloat16 *hA, *oA, *hidA, *Wqkv, *WoT, *W1T, *W2T;
    cudaGetSymbolAddress((void**)&x,    g_x);
    cudaGetSymbolAddress((void**)&h,    g_h);
    cudaGetSymbolAddress((void**)&qkv,  g_qkv);
    cudaGetSymbolAddress((void**)&hA,   g_hA);
    cudaGetSymbolAddress((void**)&oA,   g_oA);
    cudaGetSymbolAddress((void**)&hidA, g_hidA);
    cudaGetSymbolAddress((void**)&lg,   g_logits);
    cudaGetSymbolAddress((void**)&Wqkv, g_Wqkv);
    cudaGetSymbolAddress((void**)&WoT,  g_WoT);
    cudaGetSymbolAddress((void**)&W1T,  g_W1T);
    cudaGetSymbolAddress((void**)&W2T,  g_W2T);

    cudaFuncSetAttribute(gemm_mma<0>, cudaFuncAttributeMaxDynamicSharedMemorySize, GSMEM);
    cudaFuncSetAttribute(gemm_mma<1>, cudaFuncAttributeMaxDynamicSharedMemorySize, GSMEM);
    cudaFuncSetAttribute(gemm_mma<2>, cudaFuncAttributeMaxDynamicSharedMemorySize, GSMEM);

    // ---- weight prep (triple-bf16 transposed) ----
    dim3 pb(32, 8);
    for (int l = 0; l < LL; l++) {
        prep_w_kernel<<<dim3(DD/32, DD/32), pb>>>(Wq + (size_t)l*DD*DD, DD, DD,
            Wqkv + (size_t)l*K3D*K3D);
        prep_w_kernel<<<dim3(DD/32, DD/32), pb>>>(Wk + (size_t)l*DD*DD, DD, DD,
            Wqkv + (size_t)l*K3D*K3D + (size_t)DD*K3D);
        prep_w_kernel<<<dim3(DD/32, DD/32), pb>>>(Wv + (size_t)l*DD*DD, DD, DD,
            Wqkv + (size_t)l*K3D*K3D + (size_t)2*DD*K3D);
        prep_w_kernel<<<dim3(DD/32, DD/32), pb>>>(Wo + (size_t)l*DD*DD, DD, DD,
            WoT + (size_t)l*DD*K3D);
        prep_w_kernel<<<dim3(DD/32, DFF/32), pb>>>(W1 + (size_t)l*DD*DFF, DD, DFF,
            W1T + (size_t)l*DFF*K3D);
        prep_w_kernel<<<dim3(DFF/32, DD/32), pb>>>(W2 + (size_t)l*DFF*DD, DFF, DD,
            W2T + (size_t)l*DD*K3F);
    }

    embed_kernel<<<(MM * DD + 255) / 256, 256>>>(ids, tok, pos, x);

    for (int l = 0; l < LL; l++) {
        ln_triple_kernel<<<MM, 128>>>(x, ln1g + l * DD, ln1b + l * DD, hA);

        // qkv = hA @ Wqkv^T   [M,1536] fp32
        gemm_mma<0><<<dim3(K3D/256, MM/128), 256, GSMEM>>>(
            hA, K3D, Wqkv + (size_t)l*K3D*K3D, K3D, K3D,
            qkv, K3D, nullptr, nullptr, nullptr, 0);

        attn_kernel<<<BB * HH, 256>>>(qkv, oA);

        // x = x + o @ Wo + bo
        gemm_mma<1><<<dim3(DD/256, MM/128), 256, GSMEM>>>(
            oA, K3D, WoT + (size_t)l*DD*K3D, K3D, K3D,
            x, DD, bo + l * DD, x, nullptr, 0);

        ln_triple_kernel<<<MM, 128>>>(x, ln2g + l * DD, ln2b + l * DD, hA);

        // hidA = triple_bf16(gelu(hA @ W1^T + b1))
        gemm_mma<2><<<dim3(DFF/256, MM/128), 256, GSMEM>>>(
            hA, K3D, W1T + (size_t)l*DFF*K3D, K3D, K3D,
            nullptr, 0, b1 + l * DFF, nullptr, hidA, DFF);

        // x = x + hid @ W2 + b2
        gemm_mma<1><<<dim3(DD/256, MM/128), 256, GSMEM>>>(
            hidA, K3F, W2T + (size_t)l*DD*K3F, K3F, K3F,
            x, DD, b2 + l * DD, x, nullptr, 0);
    }

    ln_kernel<<<MM, 128>>>(x, lnfg, lnfb, h);
    unembed_kernel<<<MM, 128>>>(h, Wu, bu, lg);
    loss_kernel<<<MM / 4, 128>>>(lg, tgt);

    int nlog = MM * VV;
    int ncopy = out_size < nlog ? out_size : nlog;
    if (ncopy > 0)
        copy_out_kernel<<<(ncopy + 255) / 256, 256>>>(lg, out, ncopy);
    if (out_size > nlog) {
        int tail = out_size - nlog;
        write_loss_kernel<<<(tail + 127) / 128, 128>>>(out, nlog, out_size);
    }
}

// round 5
// speedup vs baseline: 1.1499x; 1.1499x over previous
#include <cuda_runtime.h>
#include <cuda_bf16.h>
#include <math.h>
#include <stdint.h>

// Problem constants
#define LL   8
#define DD   512
#define HH   8
#define DHH  64
#define SS   64
#define VV   66
#define BB   256
#define MM   (BB * SS)      // 16384 token rows
#define DFF  (4 * DD)       // 2048
#define K3D  (3 * DD)       // 1536
#define K3F  (3 * DFF)      // 6144

// ---------------- scratch (static device allocations; no cudaMalloc) -------
__device__ float g_x[(size_t)MM * DD];
__device__ float g_h[(size_t)MM * DD];
__device__ float g_qkv[(size_t)MM * K3D];           // fp32 qkv [M, 1536]
__device__ __nv_bfloat16 g_hA[(size_t)MM * K3D];    // triple-bf16 LN out [hi|lo|hi]
__device__ __nv_bfloat16 g_oA[(size_t)MM * K3D];    // triple-bf16 attn out
__device__ __nv_bfloat16 g_hidA[(size_t)MM * K3F];  // triple-bf16 gelu out
__device__ float g_logits[(size_t)MM * VV];
__device__ float g_loss;

// triple-bf16 transposed weights [N rows][3K cols], layout [hi|hi|lo]
__device__ __nv_bfloat16 g_Wqkv[(size_t)LL * K3D * K3D];
__device__ __nv_bfloat16 g_WoT [(size_t)LL * DD * K3D];
__device__ __nv_bfloat16 g_W1T [(size_t)LL * DFF * K3D];
__device__ __nv_bfloat16 g_W2T [(size_t)LL * DD * K3F];

// ============================ PTX helpers ===================================
__device__ __forceinline__ uint32_t smem_u32(const void* p) {
    uint32_t a;
    asm("{ .reg .u64 t; cvta.to.shared.u64 t, %1; cvt.u32.u64 %0, t; }"
        : "=r"(a) : "l"(p));
    return a;
}
__device__ __forceinline__ void cp16(uint32_t s, const void* g) {
    asm volatile("cp.async.cg.shared.global [%0], [%1], 16;" :: "r"(s), "l"(g));
}
__device__ __forceinline__ void cp_commit() {
    asm volatile("cp.async.commit_group;" ::: "memory");
}
template<int N>
__device__ __forceinline__ void cp_wait() {
    asm volatile("cp.async.wait_group %0;" :: "n"(N) : "memory");
}
__device__ __forceinline__ void ldsm4(uint32_t* r, uint32_t addr) {
    asm volatile("ldmatrix.sync.aligned.m8n8.x4.shared.b16 {%0,%1,%2,%3}, [%4];"
        : "=r"(r[0]), "=r"(r[1]), "=r"(r[2]), "=r"(r[3]) : "r"(addr));
}
__device__ __forceinline__ void mma16816(float* d, const uint32_t* a, uint32_t b0, uint32_t b1) {
    asm volatile(
        "mma.sync.aligned.m16n8k16.row.col.f32.bf16.bf16.f32 "
        "{%0,%1,%2,%3}, {%4,%5,%6,%7}, {%8,%9}, {%0,%1,%2,%3};"
        : "+f"(d[0]), "+f"(d[1]), "+f"(d[2]), "+f"(d[3])
        : "r"(a[0]), "r"(a[1]), "r"(a[2]), "r"(a[3]), "r"(b0), "r"(b1));
}

// ============================ HMMA GEMM =====================================
// C[M,N] = A'[M,K3] @ B'[N,K3]^T, bf16 K-major (K3 = 512 single or 1536/6144 triple)
// CTA tile 128x256, BK=64, 3-stage cp.async pipeline, 8 warps 2m x 4n, 64x64 each.
// EPI 0: C fp32
// EPI 1: C = acc + bias + res   (fp32, res==C aliasing ok)
// EPI 2: C3 = triple-bf16(gelu(acc + bias)), activation layout [hi|lo|hi]
#define STG       3
#define STG_BYTES 49152u   // A 16KB + B 32KB per stage

template<int EPI>
__global__ void __launch_bounds__(256, 1)
gemm_mma(const __nv_bfloat16* __restrict__ A, int lda,
         const __nv_bfloat16* __restrict__ B, int ldb,
         int K3,
         float* __restrict__ C, int ldc,
         const float* __restrict__ bias,
         float* __restrict__ res,
         __nv_bfloat16* __restrict__ C3, int kseg)
{
    extern __shared__ char smem[];
    const int t    = threadIdx.x;
    const int wid  = t >> 5, lane = t & 31;
    const int brow = blockIdx.y * 128;
    const int bcol = blockIdx.x * 256;
    const int wm   = (wid & 1) * 64;
    const int wn   = (wid >> 1) * 64;

    uint32_t sbase = smem_u32(smem);

    float acc[4][8][4];
    #pragma unroll
    for (int i = 0; i < 4; i++)
        #pragma unroll
        for (int j = 0; j < 8; j++)
            #pragma unroll
            for (int e = 0; e < 4; e++) acc[i][j][e] = 0.0f;

    // ---- stage loader: A 128x64 + B 256x64 bf16, SW128 swizzle -------------
    auto load_stage = [&](int s) {
        int buf = s % STG;
        int k0  = s << 6;
        uint32_t sa = sbase + buf * STG_BYTES;
        uint32_t sb = sa + 16384u;
        #pragma unroll
        for (int i = 0; i < 4; i++) {          // A: 1024 cp16
            int c   = t + (i << 8);
            int row = c >> 3;
            int c16 = c & 7;
            uint32_t off = (uint32_t)(row * 128 + c16 * 16);
            off ^= (off >> 3) & 0x70u;
            cp16(sa + off, A + (size_t)(brow + row) * lda + k0 + c16 * 8);
        }
        #pragma unroll
        for (int i = 0; i < 8; i++) {          // B: 2048 cp16
            int c   = t + (i << 8);
            int row = c >> 3;
            int c16 = c & 7;
            uint32_t off = (uint32_t)(row * 128 + c16 * 16);
            off ^= (off >> 3) & 0x70u;
            cp16(sb + off, B + (size_t)(bcol + row) * ldb + k0 + c16 * 8);
        }
        cp_commit();
    };

    const int S = K3 >> 6;

    const int lrow = ((lane >> 3) & 1) * 8 + (lane & 7);
    const int lkb  = (lane >> 4) * 16;

    load_stage(0);
    load_stage(1);

    for (int s = 0; s < S; s++) {
        int buf = s % STG;
        cp_wait<1>();
        __syncthreads();

        uint32_t sa = sbase + buf * STG_BYTES;
        uint32_t sb = sa + 16384u;

        #pragma unroll
        for (int kk = 0; kk < 4; kk++) {
            int kbyte = kk * 32 + lkb;

            uint32_t afr[4][4];
            #pragma unroll
            for (int mi = 0; mi < 4; mi++) {
                uint32_t off = (uint32_t)((wm + mi * 16 + lrow) * 128 + kbyte);
                off ^= (off >> 3) & 0x70u;
                ldsm4(afr[mi], sa + off);
            }
            uint32_t bfr[4][4];
            #pragma unroll
            for (int nj = 0; nj < 4; nj++) {
                uint32_t off = (uint32_t)((wn + nj * 16 + lrow) * 128 + kbyte);
                off ^= (off >> 3) & 0x70u;
                ldsm4(bfr[nj], sb + off);
            }
            #pragma unroll
            for (int mi = 0; mi < 4; mi++) {
                #pragma unroll
                for (int nj = 0; nj < 4; nj++) {
                    mma16816(acc[mi][2 * nj],     afr[mi], bfr[nj][0], bfr[nj][2]);
                    mma16816(acc[mi][2 * nj + 1], afr[mi], bfr[nj][1], bfr[nj][3]);
                }
            }
        }
        __syncthreads();
        if (s + 2 < S) load_stage(s + 2);
    }

    // ---- epilogue (register-resident mma layout) ----------------------------
    #pragma unroll
    for (int mi = 0; mi < 4; mi++) {
        #pragma unroll
        for (int ni = 0; ni < 8; ni++) {
            int r0 = brow + wm + mi * 16 + (lane >> 2);
            int c0 = bcol + wn + ni * 8 + ((lane & 3) << 1);
            #pragma unroll
            for (int half = 0; half < 2; half++) {
                int row = r0 + half * 8;
                float v0 = acc[mi][ni][half * 2];
                float v1 = acc[mi][ni][half * 2 + 1];
                if (EPI == 0) {
                    *(float2*)&C[(size_t)row * ldc + c0] = make_float2(v0, v1);
                } else if (EPI == 1) {
                    float2 r = *(const float2*)&res[(size_t)row * ldc + c0];
                    *(float2*)&C[(size_t)row * ldc + c0] =
                        make_float2(v0 + bias[c0] + r.x, v1 + bias[c0 + 1] + r.y);
                } else {
                    float a0 = v0 + bias[c0];
                    float a1 = v1 + bias[c0 + 1];
                    float g0 = 0.5f * a0 * (1.0f + erff(a0 * 0.70710678118654752f));
                    float g1 = 0.5f * a1 * (1.0f + erff(a1 * 0.70710678118654752f));
                    __nv_bfloat16 h0 = __float2bfloat16(g0);
                    __nv_bfloat16 l0 = __float2bfloat16(g0 - __bfloat162float(h0));
                    __nv_bfloat16 h1 = __float2bfloat16(g1);
                    __nv_bfloat16 l1 = __float2bfloat16(g1 - __bfloat162float(h1));
                    size_t ro = (size_t)row * (3 * kseg);
                    *(__nv_bfloat162*)&C3[ro + c0]            = __nv_bfloat162(h0, h1);
                    *(__nv_bfloat162*)&C3[ro + kseg + c0]     = __nv_bfloat162(l0, l1);
                    *(__nv_bfloat162*)&C3[ro + 2 * kseg + c0] = __nv_bfloat162(h0, h1);
                }
            }
        }
    }
}

// ============================ weight prep ===================================
// W[K,N] fp32 -> out[N][3K] bf16 triple [hi|hi|lo], tiled transpose
__global__ void __launch_bounds__(256) prep_w_kernel(
    const float* __restrict__ W, int K, int N, __nv_bfloat16* __restrict__ out)
{
    __shared__ float ts[32][33];
    int k0 = blockIdx.x * 32, n0 = blockIdx.y * 32;
    int tx = threadIdx.x, ty = threadIdx.y;   // 32 x 8
    #pragma unroll
    for (int i = 0; i < 32; i += 8)
        ts[ty + i][tx] = W[(size_t)(k0 + ty + i) * N + n0 + tx];
    __syncthreads();
    #pragma unroll
    for (int i = 0; i < 32; i += 8) {
        int n = n0 + ty + i, k = k0 + tx;
        float w = ts[tx][ty + i];
        __nv_bfloat16 hi = __float2bfloat16(w);
        __nv_bfloat16 lo = __float2bfloat16(w - __bfloat162float(hi));
        size_t ro = (size_t)n * (3 * K);
        out[ro + k]         = hi;
        out[ro + K + k]     = hi;
        out[ro + 2 * K + k] = lo;
    }
}

// ---------------- embedding + loss reset ------------------------------------
__global__ void __launch_bounds__(256) embed_kernel(
    const int* __restrict__ ids, const float* __restrict__ tok,
    const float* __restrict__ pos, float* __restrict__ x)
{
    int i = blockIdx.x * 256 + threadIdx.x;
    if (i == 0) g_loss = 0.0f;
    if (i >= MM * DD) return;
    int row = i / DD;
    int d   = i - row * DD;
    int s   = row % SS;
    x[i] = tok[(size_t)ids[row] * DD + d] + pos[(size_t)s * DD + d];
}

// ---------------- LayerNorm core (unbiased std, eps on std) -----------------
__device__ __forceinline__ void ln_stats(const float4& v, int t, float& mean, float& inv)
{
    float s  = v.x + v.y + v.z + v.w;
    float ss = v.x * v.x + v.y * v.y + v.z * v.z + v.w * v.w;
    #pragma unroll
    for (int o = 16; o; o >>= 1) {
        s  += __shfl_xor_sync(0xffffffffu, s,  o);
        ss += __shfl_xor_sync(0xffffffffu, ss, o);
    }
    __shared__ float sh[8];
    int wid = t >> 5, lane = t & 31;
    if (lane == 0) { sh[wid * 2] = s; sh[wid * 2 + 1] = ss; }
    __syncthreads();
    s  = sh[0] + sh[2] + sh[4] + sh[6];
    ss = sh[1] + sh[3] + sh[5] + sh[7];
    mean = s * (1.0f / DD);
    float var = (ss - s * mean) * (1.0f / (DD - 1));
    inv = 1.0f / (sqrtf(fmaxf(var, 0.0f)) + 1e-10f);
}

__global__ void __launch_bounds__(128) ln_kernel(
    const float* __restrict__ x, const float* __restrict__ g,
    const float* __restrict__ b, float* __restrict__ out)
{
    int row = blockIdx.x, t = threadIdx.x;
    float4 v = ((const float4*)(x + (size_t)row * DD))[t];
    float mean, inv;
    ln_stats(v, t, mean, inv);
    float4 gv = ((const float4*)g)[t], bv = ((const float4*)b)[t];
    float4 ov;
    ov.x = (v.x - mean) * inv * gv.x + bv.x;
    ov.y = (v.y - mean) * inv * gv.y + bv.y;
    ov.z = (v.z - mean) * inv * gv.z + bv.z;
    ov.w = (v.w - mean) * inv * gv.w + bv.w;
    ((float4*)(out + (size_t)row * DD))[t] = ov;
}

// LN -> triple bf16 [hi|lo|hi], row stride 1536
__global__ void __launch_bounds__(128) ln_triple_kernel(
    const float* __restrict__ x, const float* __restrict__ g,
    const float* __restrict__ b, __nv_bfloat16* __restrict__ out)
{
    int row = blockIdx.x, t = threadIdx.x;
    float4 v = ((const float4*)(x + (size_t)row * DD))[t];
    float mean, inv;
    ln_stats(v, t, mean, inv);
    float4 gv = ((const float4*)g)[t], bv = ((const float4*)b)[t];
    float o[4] = {
        (v.x - mean) * inv * gv.x + bv.x,
        (v.y - mean) * inv * gv.y + bv.y,
        (v.z - mean) * inv * gv.z + bv.z,
        (v.w - mean) * inv * gv.w + bv.w };
    size_t ro = (size_t)row * K3D + t * 4;
    #pragma unroll
    for (int j = 0; j < 4; j++) {
        __nv_bfloat16 hi = __float2bfloat16(o[j]);
        __nv_bfloat16 lo = __float2bfloat16(o[j] - __bfloat162float(hi));
        out[ro + j]            = hi;
        out[ro + DD + j]       = lo;
        out[ro + 2 * DD + j]   = hi;
    }
}

// ---------------- fused causal attention per (b,h) --------------------------
__global__ void __launch_bounds__(256) attn_kernel(
    const float* __restrict__ qkv, __nv_bfloat16* __restrict__ oA)
{
    int bh = blockIdx.x;
    int b  = bh >> 3;
    int h  = bh & 7;
    const float* qb = qkv + (size_t)b * SS * K3D + h * DHH;
    const float* kb = qb + DD;
    const float* vb = qb + 2 * DD;
    __nv_bfloat16* ob = oA + (size_t)b * SS * K3D + h * DHH;

    __shared__ float Ks[SS][DHH + 1];
    __shared__ float Vs[SS][DHH + 1];
    __shared__ float attn_s[8][SS];

    int tid = threadIdx.x;
    for (int i = tid; i < SS * DHH; i += 256) {
        int s = i >> 6, e = i & 63;
        Ks[s][e] = kb[(size_t)s * K3D + e];
        Vs[s][e] = vb[(size_t)s * K3D + e];
    }
    __syncthreads();

    int warp = tid >> 5, lane = tid & 31;
    const float scale = 0.044194173824159216f;  // 1/sqrt(512)

    for (int r = 0; r < 8; r++) {
        int s = warp * 8 + r;
        float q0 = qb[(size_t)s * K3D + lane];
        float q1 = qb[(size_t)s * K3D + lane + 32];

        float sc0 = 0.0f, sc1 = 0.0f;
        #pragma unroll
        for (int e = 0; e < 32; e++) {
            float qe = __shfl_sync(0xffffffffu, q0, e);
            sc0 = fmaf(qe, Ks[lane][e],      sc0);
            sc1 = fmaf(qe, Ks[lane + 32][e], sc1);
        }
        #pragma unroll
        for (int e = 0; e < 32; e++) {
            float qe = __shfl_sync(0xffffffffu, q1, e);
            sc0 = fmaf(qe, Ks[lane][e + 32],      sc0);
            sc1 = fmaf(qe, Ks[lane + 32][e + 32], sc1);
        }
        sc0 = (lane <= s)      ? sc0 * scale : -1e30f;
        sc1 = (lane + 32 <= s) ? sc1 * scale : -1e30f;

        float m = fmaxf(sc0, sc1);
        #pragma unroll
        for (int off = 16; off; off >>= 1)
            m = fmaxf(m, __shfl_xor_sync(0xffffffffu, m, off));
        float e0 = __expf(sc0 - m), e1 = __expf(sc1 - m);
        float sum = e0 + e1;
        #pragma unroll
        for (int off = 16; off; off >>= 1)
            sum += __shfl_xor_sync(0xffffffffu, sum, off);
        float invs = 1.0f / sum;
        attn_s[warp][lane]      = e0 * invs;
        attn_s[warp][lane + 32] = e1 * invs;
        __syncwarp();

        float o0 = 0.0f, o1 = 0.0f;
        #pragma unroll
        for (int tt = 0; tt < SS; tt++) {
            float a = attn_s[warp][tt];
            o0 = fmaf(a, Vs[tt][lane],      o0);
            o1 = fmaf(a, Vs[tt][lane + 32], o1);
        }
        size_t ro = (size_t)s * K3D;
        __nv_bfloat16 h0 = __float2bfloat16(o0);
        __nv_bfloat16 l0 = __float2bfloat16(o0 - __bfloat162float(h0));
        __nv_bfloat16 h1 = __float2bfloat16(o1);
        __nv_bfloat16 l1 = __float2bfloat16(o1 - __bfloat162float(h1));
        ob[ro + lane]               = h0;
        ob[ro + DD + lane]          = l0;
        ob[ro + 2 * DD + lane]      = h0;
        ob[ro + lane + 32]          = h1;
        ob[ro + DD + lane + 32]     = l1;
        ob[ro + 2 * DD + lane + 32] = h1;
        __syncwarp();
    }
}

// ---------------- unembed: 8 rows/block, Wu register-blocked ----------------
#define UROWS 8
__global__ void __launch_bounds__(128) unembed_kernel(
    const float* __restrict__ x, const float* __restrict__ Wu,
    const float* __restrict__ bu, float* __restrict__ logits)
{
    __shared__ float xs[UROWS][DD];
    int r0 = blockIdx.x * UROWS;
    for (int i = threadIdx.x; i < UROWS * DD; i += 128) {
        int r = i >> 9, k = i & 511;
        xs[r][k] = x[(size_t)(r0 + r) * DD + k];
    }
    __syncthreads();
    int c = threadIdx.x;
    if (c < VV) {
        float acc[UROWS];
        float bc = bu[c];
        #pragma unroll
        for (int r = 0; r < UROWS; r++) acc[r] = bc;
        #pragma unroll 4
        for (int k = 0; k < DD; k++) {
            float w = Wu[(size_t)k * VV + c];
            #pragma unroll
            for (int r = 0; r < UROWS; r++)
                acc[r] = fmaf(xs[r][k], w, acc[r]);
        }
        #pragma unroll
        for (int r = 0; r < UROWS; r++)
            logits[(size_t)(r0 + r) * VV + c] = acc[r];
    }
}

// ---------------- cross-entropy loss ----------------------------------------
__global__ void __launch_bounds__(128) loss_kernel(
    const float* __restrict__ logits, const int* __restrict__ tgt)
{
    int warp = threadIdx.x >> 5, lane = threadIdx.x & 31;
    int row  = blockIdx.x * 4 + warp;
    const float* lr = logits + (size_t)row * VV;

    float l0 = lr[lane];
    float l1 = lr[lane + 32];
    float l2 = (lane + 64 < VV) ? lr[lane + 64] : -1e30f;

    float m = fmaxf(fmaxf(l0, l1), l2);
    #pragma unroll
    for (int off = 16; off; off >>= 1)
        m = fmaxf(m, __shfl_xor_sync(0xffffffffu, m, off));
    float sum = expf(l0 - m) + expf(l1 - m) + ((lane + 64 < VV) ? expf(l2 - m) : 0.0f);
    #pragma unroll
    for (int off = 16; off; off >>= 1)
        sum += __shfl_xor_sync(0xffffffffu, sum, off);

    if (lane == 0) {
        float lse = m + logf(sum);
        float lt  = lr[tgt[row]];
        atomicAdd(&g_loss, lse - lt);
    }
}

// ---------------- output assembly -------------------------------------------
__global__ void __launch_bounds__(256) copy_out_kernel(
    const float* __restrict__ lg, float* __restrict__ out, int n)
{
    int i = blockIdx.x * 256 + threadIdx.x;
    if (i < n) out[i] = lg[i];
}
__global__ void __launch_bounds__(128) write_loss_kernel(
    float* __restrict__ out, int lo, int hi)
{
    int i = lo + blockIdx.x * 128 + threadIdx.x;
    if (i < hi) out[i] = g_loss * (1.0f / (float)MM);
}

// ---------------- launcher ----------------------------------------------------
#define GSMEM (STG * 49152)

extern "C" void kernel_launch(void* const* d_in, const int* in_sizes, int n_in,
                              void* d_out, int out_size)
{
    const int*   ids  = (const int*)d_in[0];
    const int*   tgt  = (const int*)d_in[1];
    const float* tok  = (const float*)d_in[2];
    const float* pos  = (const float*)d_in[3];
    const float* Wq   = (const float*)d_in[4];
    const float* Wk   = (const float*)d_in[5];
    const float* Wv   = (const float*)d_in[6];
    const float* Wo   = (const float*)d_in[7];
    const float* bo   = (const float*)d_in[8];
    const float* W1   = (const float*)d_in[9];
    const float* b1   = (const float*)d_in[10];
    const float* W2   = (const float*)d_in[11];
    const float* b2   = (const float*)d_in[12];
    const float* ln1g = (const float*)d_in[13];
    const float* ln1b = (const float*)d_in[14];
    const float* ln2g = (const float*)d_in[15];
    const float* ln2b = (const float*)d_in[16];
    const float* lnfg = (const float*)d_in[17];
    const float* lnfb = (const float*)d_in[18];
    const float* Wu   = (const float*)d_in[19];
    const float* bu   = (const float*)d_in[20];
    float* out = (float*)d_out;

    float *x, *h, *qkv, *lg;
    __nv_bfloat16 *hA, *oA, *hidA, *Wqkv, *WoT, *W1T, *W2T;
    cudaGetSymbolAddress((void**)&x,    g_x);
    cudaGetSymbolAddress((void**)&h,    g_h);
    cudaGetSymbolAddress((void**)&qkv,  g_qkv);
    cudaGetSymbolAddress((void**)&hA,   g_hA);
    cudaGetSymbolAddress((void**)&oA,   g_oA);
    cudaGetSymbolAddress((void**)&hidA, g_hidA);
    cudaGetSymbolAddress((void**)&lg,   g_logits);
    cudaGetSymbolAddress((void**)&Wqkv, g_Wqkv);
    cudaGetSymbolAddress((void**)&WoT,  g_WoT);
    cudaGetSymbolAddress((void**)&W1T,  g_W1T);
    cudaGetSymbolAddress((void**)&W2T,  g_W2T);

    cudaFuncSetAttribute(gemm_mma<0>, cudaFuncAttributeMaxDynamicSharedMemorySize, GSMEM);
    cudaFuncSetAttribute(gemm_mma<1>, cudaFuncAttributeMaxDynamicSharedMemorySize, GSMEM);
    cudaFuncSetAttribute(gemm_mma<2>, cudaFuncAttributeMaxDynamicSharedMemorySize, GSMEM);

    // ---- weight prep (triple-bf16 transposed) ----
    dim3 pb(32, 8);
    for (int l = 0; l < LL; l++) {
        prep_w_kernel<<<dim3(DD/32, DD/32), pb>>>(Wq + (size_t)l*DD*DD, DD, DD,
            Wqkv + (size_t)l*K3D*K3D);
        prep_w_kernel<<<dim3(DD/32, DD/32), pb>>>(Wk + (size_t)l*DD*DD, DD, DD,
            Wqkv + (size_t)l*K3D*K3D + (size_t)DD*K3D);
        prep_w_kernel<<<dim3(DD/32, DD/32), pb>>>(Wv + (size_t)l*DD*DD, DD, DD,
            Wqkv + (size_t)l*K3D*K3D + (size_t)2*DD*K3D);
        prep_w_kernel<<<dim3(DD/32, DD/32), pb>>>(Wo + (size_t)l*DD*DD, DD, DD,
            WoT + (size_t)l*DD*K3D);
        prep_w_kernel<<<dim3(DD/32, DFF/32), pb>>>(W1 + (size_t)l*DD*DFF, DD, DFF,
            W1T + (size_t)l*DFF*K3D);
        prep_w_kernel<<<dim3(DFF/32, DD/32), pb>>>(W2 + (size_t)l*DFF*DD, DFF, DD,
            W2T + (size_t)l*DD*K3F);
    }

    embed_kernel<<<(MM * DD + 255) / 256, 256>>>(ids, tok, pos, x);

    for (int l = 0; l < LL; l++) {
        ln_triple_kernel<<<MM, 128>>>(x, ln1g + l * DD, ln1b + l * DD, hA);

        // qkv = h_hi @ W_hi^T  — SINGLE bf16, K=512 (hi segments are first in
        // both buffers; strides stay K3D). 3x fewer MMA flops than triple.
        gemm_mma<0><<<dim3(K3D/256, MM/128), 256, GSMEM>>>(
            hA, K3D, Wqkv + (size_t)l*K3D*K3D, K3D, DD,
            qkv, K3D, nullptr, nullptr, nullptr, 0);

        attn_kernel<<<BB * HH, 256>>>(qkv, oA);

        // x = x + o @ Wo + bo   (triple-bf16, K=1536)
        gemm_mma<1><<<dim3(DD/256, MM/128), 256, GSMEM>>>(
            oA, K3D, WoT + (size_t)l*DD*K3D, K3D, K3D,
            x, DD, bo + l * DD, x, nullptr, 0);

        ln_triple_kernel<<<MM, 128>>>(x, ln2g + l * DD, ln2b + l * DD, hA);

        // hidA = triple_bf16(gelu(hA @ W1^T + b1))   (triple, K=1536)
        gemm_mma<2><<<dim3(DFF/256, MM/128), 256, GSMEM>>>(
            hA, K3D, W1T + (size_t)l*DFF*K3D, K3D, K3D,
            nullptr, 0, b1 + l * DFF, nullptr, hidA, DFF);

        // x = x + hid @ W2 + b2   (triple, K=6144)
        gemm_mma<1><<<dim3(DD/256, MM/128), 256, GSMEM>>>(
            hidA, K3F, W2T + (size_t)l*DD*K3F, K3F, K3F,
            x, DD, b2 + l * DD, x, nullptr, 0);
    }

    ln_kernel<<<MM, 128>>>(x, lnfg, lnfb, h);
    unembed_kernel<<<MM / UROWS, 128>>>(h, Wu, bu, lg);
    loss_kernel<<<MM / 4, 128>>>(lg, tgt);

    int nlog = MM * VV;
    int ncopy = out_size < nlog ? out_size : nlog;
    if (ncopy > 0)
        copy_out_kernel<<<(ncopy + 255) / 256, 256>>>(lg, out, ncopy);
    if (out_size > nlog) {
        int tail = out_size - nlog;
        write_loss_kernel<<<(tail + 127) / 128, 128>>>(out, nlog, out_size);
    }
}

// round 6
// speedup vs baseline: 1.5588x; 1.3556x over previous
#include <cuda_runtime.h>
#include <cuda_fp16.h>
#include <math.h>
#include <stdint.h>

// Problem constants
#define LL   8
#define DD   512
#define HH   8
#define DHH  64
#define SS   64
#define VV   66
#define BB   256
#define MM   (BB * SS)      // 16384 token rows
#define DFF  (4 * DD)       // 2048
#define K2D  (2 * DD)       // 1024  (double-fp16 K for D-sized inputs)
#define K2F  (2 * DFF)      // 4096  (double-fp16 K for hid inputs)
#define KQKV (3 * DD)       // 1536  (qkv output width)

// ---------------- scratch (static device allocations; no cudaMalloc) -------
__device__ float g_x[(size_t)MM * DD];
__device__ float g_h[(size_t)MM * DD];
__device__ float g_qkv[(size_t)MM * KQKV];       // fp32 qkv [M, 1536]
__device__ __half g_hA[(size_t)MM * K2D];        // double-fp16 LN out [hi|lo]
__device__ __half g_oA[(size_t)MM * K2D];        // double-fp16 attn out [hi|lo]
__device__ __half g_hidA[(size_t)MM * K2F];      // double-fp16 gelu out [hi|lo]
__device__ float g_logits[(size_t)MM * VV];
__device__ float g_loss;

// fp16 transposed weights
__device__ __half g_Wqkv[(size_t)LL * KQKV * DD];   // [1536][512] single hi
__device__ __half g_WoT [(size_t)LL * DD * K2D];    // [512][1024]  [hi|hi]
__device__ __half g_W1T [(size_t)LL * DFF * K2D];   // [2048][1024] [hi|hi]
__device__ __half g_W2T [(size_t)LL * DD * K2F];    // [512][4096]  [hi|hi]

// ============================ PTX helpers ===================================
__device__ __forceinline__ uint32_t smem_u32(const void* p) {
    uint32_t a;
    asm("{ .reg .u64 t; cvta.to.shared.u64 t, %1; cvt.u32.u64 %0, t; }"
        : "=r"(a) : "l"(p));
    return a;
}
__device__ __forceinline__ void cp16(uint32_t s, const void* g) {
    asm volatile("cp.async.cg.shared.global [%0], [%1], 16;" :: "r"(s), "l"(g));
}
__device__ __forceinline__ void cp_commit() {
    asm volatile("cp.async.commit_group;" ::: "memory");
}
template<int N>
__device__ __forceinline__ void cp_wait() {
    asm volatile("cp.async.wait_group %0;" :: "n"(N) : "memory");
}
__device__ __forceinline__ void ldsm4(uint32_t* r, uint32_t addr) {
    asm volatile("ldmatrix.sync.aligned.m8n8.x4.shared.b16 {%0,%1,%2,%3}, [%4];"
        : "=r"(r[0]), "=r"(r[1]), "=r"(r[2]), "=r"(r[3]) : "r"(addr));
}
__device__ __forceinline__ void mma16816(float* d, const uint32_t* a, uint32_t b0, uint32_t b1) {
    asm volatile(
        "mma.sync.aligned.m16n8k16.row.col.f32.f16.f16.f32 "
        "{%0,%1,%2,%3}, {%4,%5,%6,%7}, {%8,%9}, {%0,%1,%2,%3};"
        : "+f"(d[0]), "+f"(d[1]), "+f"(d[2]), "+f"(d[3])
        : "r"(a[0]), "r"(a[1]), "r"(a[2]), "r"(a[3]), "r"(b0), "r"(b1));
}
__device__ __forceinline__ void split_h(float v, __half& hi, __half& lo) {
    hi = __float2half_rn(v);
    lo = __float2half_rn(v - __half2float(hi));
}

// ============================ HMMA GEMM =====================================
// C[M,N] = A'[M,K3] @ B'[N,K3]^T, fp16 K-major.
// CTA tile 128x256, BK=64, 3-stage cp.async pipeline, 8 warps 2m x 4n, 64x64 each.
// EPI 0: C fp32
// EPI 1: C = acc + bias + res   (fp32, res==C aliasing ok)
// EPI 2: C2 = double-fp16(gelu(acc + bias)) [hi|lo], row stride 2*kseg
#define STG       3
#define STG_BYTES 49152u   // A 16KB + B 32KB per stage

template<int EPI>
__global__ void __launch_bounds__(256, 1)
gemm_mma(const __half* __restrict__ A, int lda,
         const __half* __restrict__ B, int ldb,
         int K3,
         float* __restrict__ C, int ldc,
         const float* __restrict__ bias,
         float* __restrict__ res,
         __half* __restrict__ C2, int kseg)
{
    extern __shared__ char smem[];
    const int t    = threadIdx.x;
    const int wid  = t >> 5, lane = t & 31;
    const int brow = blockIdx.y * 128;
    const int bcol = blockIdx.x * 256;
    const int wm   = (wid & 1) * 64;
    const int wn   = (wid >> 1) * 64;

    uint32_t sbase = smem_u32(smem);

    float acc[4][8][4];
    #pragma unroll
    for (int i = 0; i < 4; i++)
        #pragma unroll
        for (int j = 0; j < 8; j++)
            #pragma unroll
            for (int e = 0; e < 4; e++) acc[i][j][e] = 0.0f;

    // ---- stage loader: A 128x64 + B 256x64 fp16, SW128 swizzle -------------
    auto load_stage = [&](int s) {
        int buf = s % STG;
        int k0  = s << 6;
        uint32_t sa = sbase + buf * STG_BYTES;
        uint32_t sb = sa + 16384u;
        #pragma unroll
        for (int i = 0; i < 4; i++) {          // A: 1024 cp16
            int c   = t + (i << 8);
            int row = c >> 3;
            int c16 = c & 7;
            uint32_t off = (uint32_t)(row * 128 + c16 * 16);
            off ^= (off >> 3) & 0x70u;
            cp16(sa + off, A + (size_t)(brow + row) * lda + k0 + c16 * 8);
        }
        #pragma unroll
        for (int i = 0; i < 8; i++) {          // B: 2048 cp16
            int c   = t + (i << 8);
            int row = c >> 3;
            int c16 = c & 7;
            uint32_t off = (uint32_t)(row * 128 + c16 * 16);
            off ^= (off >> 3) & 0x70u;
            cp16(sb + off, B + (size_t)(bcol + row) * ldb + k0 + c16 * 8);
        }
        cp_commit();
    };

    const int S = K3 >> 6;

    const int lrow = ((lane >> 3) & 1) * 8 + (lane & 7);
    const int lkb  = (lane >> 4) * 16;

    load_stage(0);
    load_stage(1);

    for (int s = 0; s < S; s++) {
        int buf = s % STG;
        cp_wait<1>();
        __syncthreads();

        uint32_t sa = sbase + buf * STG_BYTES;
        uint32_t sb = sa + 16384u;

        #pragma unroll
        for (int kk = 0; kk < 4; kk++) {
            int kbyte = kk * 32 + lkb;

            uint32_t afr[4][4];
            #pragma unroll
            for (int mi = 0; mi < 4; mi++) {
                uint32_t off = (uint32_t)((wm + mi * 16 + lrow) * 128 + kbyte);
                off ^= (off >> 3) & 0x70u;
                ldsm4(afr[mi], sa + off);
            }
            uint32_t bfr[4][4];
            #pragma unroll
            for (int nj = 0; nj < 4; nj++) {
                uint32_t off = (uint32_t)((wn + nj * 16 + lrow) * 128 + kbyte);
                off ^= (off >> 3) & 0x70u;
                ldsm4(bfr[nj], sb + off);
            }
            #pragma unroll
            for (int mi = 0; mi < 4; mi++) {
                #pragma unroll
                for (int nj = 0; nj < 4; nj++) {
                    mma16816(acc[mi][2 * nj],     afr[mi], bfr[nj][0], bfr[nj][2]);
                    mma16816(acc[mi][2 * nj + 1], afr[mi], bfr[nj][1], bfr[nj][3]);
                }
            }
        }
        __syncthreads();
        if (s + 2 < S) load_stage(s + 2);
    }

    // ---- epilogue (register-resident mma layout) ----------------------------
    #pragma unroll
    for (int mi = 0; mi < 4; mi++) {
        #pragma unroll
        for (int ni = 0; ni < 8; ni++) {
            int r0 = brow + wm + mi * 16 + (lane >> 2);
            int c0 = bcol + wn + ni * 8 + ((lane & 3) << 1);
            #pragma unroll
            for (int half = 0; half < 2; half++) {
                int row = r0 + half * 8;
                float v0 = acc[mi][ni][half * 2];
                float v1 = acc[mi][ni][half * 2 + 1];
                if (EPI == 0) {
                    *(float2*)&C[(size_t)row * ldc + c0] = make_float2(v0, v1);
                } else if (EPI == 1) {
                    float2 bv = *(const float2*)&bias[c0];
                    float2 r  = *(const float2*)&res[(size_t)row * ldc + c0];
                    *(float2*)&C[(size_t)row * ldc + c0] =
                        make_float2(v0 + bv.x + r.x, v1 + bv.y + r.y);
                } else {
                    float2 bv = *(const float2*)&bias[c0];
                    float a0 = v0 + bv.x;
                    float a1 = v1 + bv.y;
                    float g0 = 0.5f * a0 * (1.0f + erff(a0 * 0.70710678118654752f));
                    float g1 = 0.5f * a1 * (1.0f + erff(a1 * 0.70710678118654752f));
                    __half h0, l0, h1, l1;
                    split_h(g0, h0, l0);
                    split_h(g1, h1, l1);
                    size_t ro = (size_t)row * (2 * kseg);
                    *(__half2*)&C2[ro + c0]        = __halves2half2(h0, h1);
                    *(__half2*)&C2[ro + kseg + c0] = __halves2half2(l0, l1);
                }
            }
        }
    }
}

// ============================ weight prep ===================================
// Single: W[K,N] fp32 (layer l at l*K*N) -> out[N][K] fp16 hi, transposed.
// grid.z = layer; outLayer = per-layer element stride of out.
__global__ void __launch_bounds__(256) prep_w_single(
    const float* __restrict__ W, int K, int N,
    __half* __restrict__ out, size_t outLayer)
{
    __shared__ float ts[32][33];
    int l  = blockIdx.z;
    const float* Wl = W + (size_t)l * K * N;
    __half* ol = out + (size_t)l * outLayer;
    int k0 = blockIdx.x * 32, n0 = blockIdx.y * 32;
    int tx = threadIdx.x, ty = threadIdx.y;   // 32 x 8
    #pragma unroll
    for (int i = 0; i < 32; i += 8)
        ts[ty + i][tx] = Wl[(size_t)(k0 + ty + i) * N + n0 + tx];
    __syncthreads();
    #pragma unroll
    for (int i = 0; i < 32; i += 8) {
        int n = n0 + ty + i, k = k0 + tx;
        ol[(size_t)n * K + k] = __float2half_rn(ts[tx][ty + i]);
    }
}

// Double: W[K,N] fp32 -> out[N][2K] fp16 [hi|hi] transposed.
__global__ void __launch_bounds__(256) prep_w_double(
    const float* __restrict__ W, int K, int N,
    __half* __restrict__ out, size_t outLayer)
{
    __shared__ float ts[32][33];
    int l  = blockIdx.z;
    const float* Wl = W + (size_t)l * K * N;
    __half* ol = out + (size_t)l * outLayer;
    int k0 = blockIdx.x * 32, n0 = blockIdx.y * 32;
    int tx = threadIdx.x, ty = threadIdx.y;
    #pragma unroll
    for (int i = 0; i < 32; i += 8)
        ts[ty + i][tx] = Wl[(size_t)(k0 + ty + i) * N + n0 + tx];
    __syncthreads();
    #pragma unroll
    for (int i = 0; i < 32; i += 8) {
        int n = n0 + ty + i, k = k0 + tx;
        __half hi = __float2half_rn(ts[tx][ty + i]);
        size_t ro = (size_t)n * (2 * K);
        ol[ro + k]     = hi;
        ol[ro + K + k] = hi;
    }
}

// ---------------- embedding + loss reset ------------------------------------
__global__ void __launch_bounds__(256) embed_kernel(
    const int* __restrict__ ids, const float* __restrict__ tok,
    const float* __restrict__ pos, float* __restrict__ x)
{
    int i = blockIdx.x * 256 + threadIdx.x;
    if (i == 0) g_loss = 0.0f;
    if (i >= MM * DD) return;
    int row = i / DD;
    int d   = i - row * DD;
    int s   = row % SS;
    x[i] = tok[(size_t)ids[row] * DD + d] + pos[(size_t)s * DD + d];
}

// ---------------- LayerNorm core (unbiased std, eps on std) -----------------
__device__ __forceinline__ void ln_stats(const float4& v, int t, float& mean, float& inv)
{
    float s  = v.x + v.y + v.z + v.w;
    float ss = v.x * v.x + v.y * v.y + v.z * v.z + v.w * v.w;
    #pragma unroll
    for (int o = 16; o; o >>= 1) {
        s  += __shfl_xor_sync(0xffffffffu, s,  o);
        ss += __shfl_xor_sync(0xffffffffu, ss, o);
    }
    __shared__ float sh[8];
    int wid = t >> 5, lane = t & 31;
    if (lane == 0) { sh[wid * 2] = s; sh[wid * 2 + 1] = ss; }
    __syncthreads();
    s  = sh[0] + sh[2] + sh[4] + sh[6];
    ss = sh[1] + sh[3] + sh[5] + sh[7];
    mean = s * (1.0f / DD);
    float var = (ss - s * mean) * (1.0f / (DD - 1));
    inv = 1.0f / (sqrtf(fmaxf(var, 0.0f)) + 1e-10f);
}

__global__ void __launch_bounds__(128) ln_kernel(
    const float* __restrict__ x, const float* __restrict__ g,
    const float* __restrict__ b, float* __restrict__ out)
{
    int row = blockIdx.x, t = threadIdx.x;
    float4 v = ((const float4*)(x + (size_t)row * DD))[t];
    float mean, inv;
    ln_stats(v, t, mean, inv);
    float4 gv = ((const float4*)g)[t], bv = ((const float4*)b)[t];
    float4 ov;
    ov.x = (v.x - mean) * inv * gv.x + bv.x;
    ov.y = (v.y - mean) * inv * gv.y + bv.y;
    ov.z = (v.z - mean) * inv * gv.z + bv.z;
    ov.w = (v.w - mean) * inv * gv.w + bv.w;
    ((float4*)(out + (size_t)row * DD))[t] = ov;
}

// LN -> double fp16 [hi|lo], row stride 1024
__global__ void __launch_bounds__(128) ln_double_kernel(
    const float* __restrict__ x, const float* __restrict__ g,
    const float* __restrict__ b, __half* __restrict__ out)
{
    int row = blockIdx.x, t = threadIdx.x;
    float4 v = ((const float4*)(x + (size_t)row * DD))[t];
    float mean, inv;
    ln_stats(v, t, mean, inv);
    float4 gv = ((const float4*)g)[t], bv = ((const float4*)b)[t];
    float o[4] = {
        (v.x - mean) * inv * gv.x + bv.x,
        (v.y - mean) * inv * gv.y + bv.y,
        (v.z - mean) * inv * gv.z + bv.z,
        (v.w - mean) * inv * gv.w + bv.w };
    __half hi[4], lo[4];
    #pragma unroll
    for (int j = 0; j < 4; j++) split_h(o[j], hi[j], lo[j]);
    size_t ro = (size_t)row * K2D + t * 4;
    *(__half2*)&out[ro]            = __halves2half2(hi[0], hi[1]);
    *(__half2*)&out[ro + 2]        = __halves2half2(hi[2], hi[3]);
    *(__half2*)&out[ro + DD]       = __halves2half2(lo[0], lo[1]);
    *(__half2*)&out[ro + DD + 2]   = __halves2half2(lo[2], lo[3]);
}

// ---------------- fused causal attention per (b,h) --------------------------
// reads qkv fp32 [M,1536] (q|k|v), writes double-fp16 o [M,1024] = [hi|lo]
__global__ void __launch_bounds__(256) attn_kernel(
    const float* __restrict__ qkv, __half* __restrict__ oA)
{
    int bh = blockIdx.x;
    int b  = bh >> 3;
    int h  = bh & 7;
    const float* qb = qkv + (size_t)b * SS * KQKV + h * DHH;
    const float* kb = qb + DD;
    const float* vb = qb + 2 * DD;
    __half* ob = oA + (size_t)b * SS * K2D + h * DHH;

    __shared__ float Ks[SS][DHH + 1];
    __shared__ float Vs[SS][DHH + 1];
    __shared__ float attn_s[8][SS];

    int tid = threadIdx.x;
    for (int i = tid; i < SS * DHH; i += 256) {
        int s = i >> 6, e = i & 63;
        Ks[s][e] = kb[(size_t)s * KQKV + e];
        Vs[s][e] = vb[(size_t)s * KQKV + e];
    }
    __syncthreads();

    int warp = tid >> 5, lane = tid & 31;
    const float scale = 0.044194173824159216f;  // 1/sqrt(512)

    for (int r = 0; r < 8; r++) {
        int s = warp * 8 + r;
        float q0 = qb[(size_t)s * KQKV + lane];
        float q1 = qb[(size_t)s * KQKV + lane + 32];

        float sc0 = 0.0f, sc1 = 0.0f;
        #pragma unroll
        for (int e = 0; e < 32; e++) {
            float qe = __shfl_sync(0xffffffffu, q0, e);
            sc0 = fmaf(qe, Ks[lane][e],      sc0);
            sc1 = fmaf(qe, Ks[lane + 32][e], sc1);
        }
        #pragma unroll
        for (int e = 0; e < 32; e++) {
            float qe = __shfl_sync(0xffffffffu, q1, e);
            sc0 = fmaf(qe, Ks[lane][e + 32],      sc0);
            sc1 = fmaf(qe, Ks[lane + 32][e + 32], sc1);
        }
        sc0 = (lane <= s)      ? sc0 * scale : -1e30f;
        sc1 = (lane + 32 <= s) ? sc1 * scale : -1e30f;

        float m = fmaxf(sc0, sc1);
        #pragma unroll
        for (int off = 16; off; off >>= 1)
            m = fmaxf(m, __shfl_xor_sync(0xffffffffu, m, off));
        float e0 = __expf(sc0 - m), e1 = __expf(sc1 - m);
        float sum = e0 + e1;
        #pragma unroll
        for (int off = 16; off; off >>= 1)
            sum += __shfl_xor_sync(0xffffffffu, sum, off);
        float invs = 1.0f / sum;
        attn_s[warp][lane]      = e0 * invs;
        attn_s[warp][lane + 32] = e1 * invs;
        __syncwarp();

        float o0 = 0.0f, o1 = 0.0f;
        #pragma unroll
        for (int tt = 0; tt < SS; tt++) {
            float a = attn_s[warp][tt];
            o0 = fmaf(a, Vs[tt][lane],      o0);
            o1 = fmaf(a, Vs[tt][lane + 32], o1);
        }
        size_t ro = (size_t)s * K2D;
        __half h0, l0, h1, l1;
        split_h(o0, h0, l0);
        split_h(o1, h1, l1);
        ob[ro + lane]           = h0;
        ob[ro + DD + lane]      = l0;
        ob[ro + lane + 32]      = h1;
        ob[ro + DD + lane + 32] = l1;
        __syncwarp();
    }
}

// ---------------- unembed: 16 rows/block, Wu register-blocked ---------------
#define UROWS 16
__global__ void __launch_bounds__(128) unembed_kernel(
    const float* __restrict__ x, const float* __restrict__ Wu,
    const float* __restrict__ bu, float* __restrict__ logits)
{
    __shared__ float xs[UROWS][DD];
    int r0 = blockIdx.x * UROWS;
    const float4* src = (const float4*)(x + (size_t)r0 * DD);
    float4* dst = (float4*)&xs[0][0];
    for (int i = threadIdx.x; i < UROWS * DD / 4; i += 128)
        dst[i] = src[i];
    __syncthreads();
    int c = threadIdx.x;
    if (c < VV) {
        float acc[UROWS];
        float bc = bu[c];
        #pragma unroll
        for (int r = 0; r < UROWS; r++) acc[r] = bc;
        #pragma unroll 4
        for (int k = 0; k < DD; k++) {
            float w = Wu[(size_t)k * VV + c];
            #pragma unroll
            for (int r = 0; r < UROWS; r++)
                acc[r] = fmaf(xs[r][k], w, acc[r]);
        }
        #pragma unroll
        for (int r = 0; r < UROWS; r++)
            logits[(size_t)(r0 + r) * VV + c] = acc[r];
    }
}

// ---------------- cross-entropy loss ----------------------------------------
__global__ void __launch_bounds__(128) loss_kernel(
    const float* __restrict__ logits, const int* __restrict__ tgt)
{
    int warp = threadIdx.x >> 5, lane = threadIdx.x & 31;
    int row  = blockIdx.x * 4 + warp;
    const float* lr = logits + (size_t)row * VV;

    float l0 = lr[lane];
    float l1 = lr[lane + 32];
    float l2 = (lane + 64 < VV) ? lr[lane + 64] : -1e30f;

    float m = fmaxf(fmaxf(l0, l1), l2);
    #pragma unroll
    for (int off = 16; off; off >>= 1)
        m = fmaxf(m, __shfl_xor_sync(0xffffffffu, m, off));
    float sum = expf(l0 - m) + expf(l1 - m) + ((lane + 64 < VV) ? expf(l2 - m) : 0.0f);
    #pragma unroll
    for (int off = 16; off; off >>= 1)
        sum += __shfl_xor_sync(0xffffffffu, sum, off);

    if (lane == 0) {
        float lse = m + logf(sum);
        float lt  = lr[tgt[row]];
        atomicAdd(&g_loss, lse - lt);
    }
}

// ---------------- output assembly -------------------------------------------
__global__ void __launch_bounds__(256) copy_out_kernel(
    const float* __restrict__ lg, float* __restrict__ out, int n)
{
    int i = blockIdx.x * 256 + threadIdx.x;
    if (i < n) out[i] = lg[i];
}
__global__ void __launch_bounds__(128) write_loss_kernel(
    float* __restrict__ out, int lo, int hi)
{
    int i = lo + blockIdx.x * 128 + threadIdx.x;
    if (i < hi) out[i] = g_loss * (1.0f / (float)MM);
}

// ---------------- launcher ----------------------------------------------------
#define GSMEM (STG * 49152)

extern "C" void kernel_launch(void* const* d_in, const int* in_sizes, int n_in,
                              void* d_out, int out_size)
{
    const int*   ids  = (const int*)d_in[0];
    const int*   tgt  = (const int*)d_in[1];
    const float* tok  = (const float*)d_in[2];
    const float* pos  = (const float*)d_in[3];
    const float* Wq   = (const float*)d_in[4];
    const float* Wk   = (const float*)d_in[5];
    const float* Wv   = (const float*)d_in[6];
    const float* Wo   = (const float*)d_in[7];
    const float* bo   = (const float*)d_in[8];
    const float* W1   = (const float*)d_in[9];
    const float* b1   = (const float*)d_in[10];
    const float* W2   = (const float*)d_in[11];
    const float* b2   = (const float*)d_in[12];
    const float* ln1g = (const float*)d_in[13];
    const float* ln1b = (const float*)d_in[14];
    const float* ln2g = (const float*)d_in[15];
    const float* ln2b = (const float*)d_in[16];
    const float* lnfg = (const float*)d_in[17];
    const float* lnfb = (const float*)d_in[18];
    const float* Wu   = (const float*)d_in[19];
    const float* bu   = (const float*)d_in[20];
    float* out = (float*)d_out;

    float *x, *h, *qkv, *lg;
    __half *hA, *oA, *hidA, *Wqkv, *WoT, *W1T, *W2T;
    cudaGetSymbolAddress((void**)&x,    g_x);
    cudaGetSymbolAddress((void**)&h,    g_h);
    cudaGetSymbolAddress((void**)&qkv,  g_qkv);
    cudaGetSymbolAddress((void**)&hA,   g_hA);
    cudaGetSymbolAddress((void**)&oA,   g_oA);
    cudaGetSymbolAddress((void**)&hidA, g_hidA);
    cudaGetSymbolAddress((void**)&lg,   g_logits);
    cudaGetSymbolAddress((void**)&Wqkv, g_Wqkv);
    cudaGetSymbolAddress((void**)&WoT,  g_WoT);
    cudaGetSymbolAddress((void**)&W1T,  g_W1T);
    cudaGetSymbolAddress((void**)&W2T,  g_W2T);

    cudaFuncSetAttribute(gemm_mma<0>, cudaFuncAttributeMaxDynamicSharedMemorySize, GSMEM);
    cudaFuncSetAttribute(gemm_mma<1>, cudaFuncAttributeMaxDynamicSharedMemorySize, GSMEM);
    cudaFuncSetAttribute(gemm_mma<2>, cudaFuncAttributeMaxDynamicSharedMemorySize, GSMEM);

    // logits destination: write directly into d_out when it holds all logits
    int nlog = MM * VV;
    float* logits_dst = (out_size >= nlog) ? out : lg;

    // ---- weight prep: 6 launches total (grid.z = layer) ----
    dim3 pb(32, 8);
    // Wqkv single fp16: parts q/k/v at row offsets 0/512/1024 of [1536][512]
    prep_w_single<<<dim3(DD/32, DD/32, LL), pb>>>(Wq, DD, DD,
        Wqkv,                         (size_t)KQKV * DD);
    prep_w_single<<<dim3(DD/32, DD/32, LL), pb>>>(Wk, DD, DD,
        Wqkv + (size_t)DD * DD,       (size_t)KQKV * DD);
    prep_w_single<<<dim3(DD/32, DD/32, LL), pb>>>(Wv, DD, DD,
        Wqkv + (size_t)2 * DD * DD,   (size_t)KQKV * DD);
    prep_w_double<<<dim3(DD/32, DD/32, LL), pb>>>(Wo, DD, DD,
        WoT,  (size_t)DD * K2D);
    prep_w_double<<<dim3(DD/32, DFF/32, LL), pb>>>(W1, DD, DFF,
        W1T,  (size_t)DFF * K2D);
    prep_w_double<<<dim3(DFF/32, DD/32, LL), pb>>>(W2, DFF, DD,
        W2T,  (size_t)DD * K2F);

    embed_kernel<<<(MM * DD + 255) / 256, 256>>>(ids, tok, pos, x);

    for (int l = 0; l < LL; l++) {
        ln_double_kernel<<<MM, 128>>>(x, ln1g + l * DD, ln1b + l * DD, hA);

        // qkv = h_hi @ Wqkv^T   single fp16, K=512
        gemm_mma<0><<<dim3(KQKV/256, MM/128), 256, GSMEM>>>(
            hA, K2D, Wqkv + (size_t)l*KQKV*DD, DD, DD,
            qkv, KQKV, nullptr, nullptr, nullptr, 0);

        attn_kernel<<<BB * HH, 256>>>(qkv, oA);

        // x = x + o @ Wo + bo    double fp16, K=1024
        gemm_mma<1><<<dim3(DD/256, MM/128), 256, GSMEM>>>(
            oA, K2D, WoT + (size_t)l*DD*K2D, K2D, K2D,
            x, DD, bo + l * DD, x, nullptr, 0);

        ln_double_kernel<<<MM, 128>>>(x, ln2g + l * DD, ln2b + l * DD, hA);

        // hidA = double_fp16(gelu(hA @ W1^T + b1))   double, K=1024
        gemm_mma<2><<<dim3(DFF/256, MM/128), 256, GSMEM>>>(
            hA, K2D, W1T + (size_t)l*DFF*K2D, K2D, K2D,
            nullptr, 0, b1 + l * DFF, nullptr, hidA, DFF);

        // x = x + hid @ W2 + b2   double, K=4096
        gemm_mma<1><<<dim3(DD/256, MM/128), 256, GSMEM>>>(
            hidA, K2F, W2T + (size_t)l*DD*K2F, K2F, K2F,
            x, DD, b2 + l * DD, x, nullptr, 0);
    }

    ln_kernel<<<MM, 128>>>(x, lnfg, lnfb, h);
    unembed_kernel<<<MM / UROWS, 128>>>(h, Wu, bu, logits_dst);
    loss_kernel<<<MM / 4, 128>>>(logits_dst, tgt);

    if (logits_dst != out) {
        int ncopy = out_size < nlog ? out_size : nlog;
        if (ncopy > 0)
            copy_out_kernel<<<(ncopy + 255) / 256, 256>>>(lg, out, ncopy);
    }
    if (out_size > nlog) {
        int tail = out_size - nlog;
        write_loss_kernel<<<(tail + 127) / 128, 128>>>(out, nlog, out_size);
    }
}

// round 7
// speedup vs baseline: 1.9154x; 1.2288x over previous
#include <cuda_runtime.h>
#include <cuda_fp16.h>
#include <math.h>
#include <stdint.h>

// Problem constants
#define LL   8
#define DD   512
#define HH   8
#define DHH  64
#define SS   64
#define VV   66
#define BB   256
#define MM   (BB * SS)      // 16384 token rows
#define DFF  (4 * DD)       // 2048
#define K2D  (2 * DD)       // 1024  (double-fp16 K for LN2 out)
#define KQKV (3 * DD)       // 1536  (qkv output width)

// ---------------- scratch (static device allocations; no cudaMalloc) -------
__device__ float g_x[(size_t)MM * DD];
__device__ float g_h[(size_t)MM * DD];
__device__ __half g_qkv[(size_t)MM * KQKV];      // fp16 qkv [M, 1536]
__device__ __half g_hA1[(size_t)MM * DD];        // single-fp16 LN1 out
__device__ __half g_hA2[(size_t)MM * K2D];       // double-fp16 LN2 out [hi|lo]
__device__ __half g_oA[(size_t)MM * DD];         // single-fp16 attn out
__device__ __half g_hidA[(size_t)MM * DFF];      // single-fp16 gelu out
__device__ float g_logits[(size_t)MM * VV];
__device__ float g_loss;

// fp16 transposed weights
__device__ __half g_Wqkv[(size_t)LL * KQKV * DD];   // [1536][512] single
__device__ __half g_WoT [(size_t)LL * DD * DD];     // [512][512]  single
__device__ __half g_W1T [(size_t)LL * DFF * K2D];   // [2048][1024] [hi|hi]
__device__ __half g_W2T [(size_t)LL * DD * DFF];    // [512][2048] single

// ============================ PTX helpers ===================================
__device__ __forceinline__ uint32_t smem_u32(const void* p) {
    uint32_t a;
    asm("{ .reg .u64 t; cvta.to.shared.u64 t, %1; cvt.u32.u64 %0, t; }"
        : "=r"(a) : "l"(p));
    return a;
}
__device__ __forceinline__ void cp16(uint32_t s, const void* g) {
    asm volatile("cp.async.cg.shared.global [%0], [%1], 16;" :: "r"(s), "l"(g));
}
__device__ __forceinline__ void cp_commit() {
    asm volatile("cp.async.commit_group;" ::: "memory");
}
template<int N>
__device__ __forceinline__ void cp_wait() {
    asm volatile("cp.async.wait_group %0;" :: "n"(N) : "memory");
}
__device__ __forceinline__ void ldsm4(uint32_t* r, uint32_t addr) {
    asm volatile("ldmatrix.sync.aligned.m8n8.x4.shared.b16 {%0,%1,%2,%3}, [%4];"
        : "=r"(r[0]), "=r"(r[1]), "=r"(r[2]), "=r"(r[3]) : "r"(addr));
}
__device__ __forceinline__ void mma16816(float* d, const uint32_t* a, uint32_t b0, uint32_t b1) {
    asm volatile(
        "mma.sync.aligned.m16n8k16.row.col.f32.f16.f16.f32 "
        "{%0,%1,%2,%3}, {%4,%5,%6,%7}, {%8,%9}, {%0,%1,%2,%3};"
        : "+f"(d[0]), "+f"(d[1]), "+f"(d[2]), "+f"(d[3])
        : "r"(a[0]), "r"(a[1]), "r"(a[2]), "r"(a[3]), "r"(b0), "r"(b1));
}
__device__ __forceinline__ void split_h(float v, __half& hi, __half& lo) {
    hi = __float2half_rn(v);
    lo = __float2half_rn(v - __half2float(hi));
}

// ============================ HMMA GEMM =====================================
// C[M,N] = A[M,K3] @ B[N,K3]^T, fp16 K-major.
// CTA tile 128x256, BK=64, 3-stage cp.async pipeline, 8 warps 2m x 4n, 64x64 each.
// EPI 0: C2 fp16 = acc                         (qkv path)
// EPI 1: C fp32 = acc + bias + res             (res==C aliasing ok)
// EPI 2: C2 fp16 = gelu(acc + bias)            (MLP hid path)
#define STG       3
#define STG_BYTES 49152u   // A 16KB + B 32KB per stage

template<int EPI>
__global__ void __launch_bounds__(256, 1)
gemm_mma(const __half* __restrict__ A, int lda,
         const __half* __restrict__ B, int ldb,
         int K3,
         float* __restrict__ C, __half* __restrict__ C2, int ldc,
         const float* __restrict__ bias,
         float* __restrict__ res)
{
    extern __shared__ char smem[];
    const int t    = threadIdx.x;
    const int wid  = t >> 5, lane = t & 31;
    const int brow = blockIdx.y * 128;
    const int bcol = blockIdx.x * 256;
    const int wm   = (wid & 1) * 64;
    const int wn   = (wid >> 1) * 64;

    uint32_t sbase = smem_u32(smem);

    float acc[4][8][4];
    #pragma unroll
    for (int i = 0; i < 4; i++)
        #pragma unroll
        for (int j = 0; j < 8; j++)
            #pragma unroll
            for (int e = 0; e < 4; e++) acc[i][j][e] = 0.0f;

    // ---- stage loader: A 128x64 + B 256x64 fp16, SW128 swizzle -------------
    auto load_stage = [&](int s) {
        int buf = s % STG;
        int k0  = s << 6;
        uint32_t sa = sbase + buf * STG_BYTES;
        uint32_t sb = sa + 16384u;
        #pragma unroll
        for (int i = 0; i < 4; i++) {          // A: 1024 cp16
            int c   = t + (i << 8);
            int row = c >> 3;
            int c16 = c & 7;
            uint32_t off = (uint32_t)(row * 128 + c16 * 16);
            off ^= (off >> 3) & 0x70u;
            cp16(sa + off, A + (size_t)(brow + row) * lda + k0 + c16 * 8);
        }
        #pragma unroll
        for (int i = 0; i < 8; i++) {          // B: 2048 cp16
            int c   = t + (i << 8);
            int row = c >> 3;
            int c16 = c & 7;
            uint32_t off = (uint32_t)(row * 128 + c16 * 16);
            off ^= (off >> 3) & 0x70u;
            cp16(sb + off, B + (size_t)(bcol + row) * ldb + k0 + c16 * 8);
        }
        cp_commit();
    };

    const int S = K3 >> 6;

    const int lrow = ((lane >> 3) & 1) * 8 + (lane & 7);
    const int lkb  = (lane >> 4) * 16;

    load_stage(0);
    load_stage(1);

    for (int s = 0; s < S; s++) {
        int buf = s % STG;
        cp_wait<1>();
        __syncthreads();

        uint32_t sa = sbase + buf * STG_BYTES;
        uint32_t sb = sa + 16384u;

        #pragma unroll
        for (int kk = 0; kk < 4; kk++) {
            int kbyte = kk * 32 + lkb;

            uint32_t afr[4][4];
            #pragma unroll
            for (int mi = 0; mi < 4; mi++) {
                uint32_t off = (uint32_t)((wm + mi * 16 + lrow) * 128 + kbyte);
                off ^= (off >> 3) & 0x70u;
                ldsm4(afr[mi], sa + off);
            }
            uint32_t bfr[4][4];
            #pragma unroll
            for (int nj = 0; nj < 4; nj++) {
                uint32_t off = (uint32_t)((wn + nj * 16 + lrow) * 128 + kbyte);
                off ^= (off >> 3) & 0x70u;
                ldsm4(bfr[nj], sb + off);
            }
            #pragma unroll
            for (int mi = 0; mi < 4; mi++) {
                #pragma unroll
                for (int nj = 0; nj < 4; nj++) {
                    mma16816(acc[mi][2 * nj],     afr[mi], bfr[nj][0], bfr[nj][2]);
                    mma16816(acc[mi][2 * nj + 1], afr[mi], bfr[nj][1], bfr[nj][3]);
                }
            }
        }
        __syncthreads();
        if (s + 2 < S) load_stage(s + 2);
    }

    // ---- epilogue (register-resident mma layout) ----------------------------
    #pragma unroll
    for (int mi = 0; mi < 4; mi++) {
        #pragma unroll
        for (int ni = 0; ni < 8; ni++) {
            int r0 = brow + wm + mi * 16 + (lane >> 2);
            int c0 = bcol + wn + ni * 8 + ((lane & 3) << 1);
            #pragma unroll
            for (int half = 0; half < 2; half++) {
                int row = r0 + half * 8;
                float v0 = acc[mi][ni][half * 2];
                float v1 = acc[mi][ni][half * 2 + 1];
                if (EPI == 0) {
                    *(__half2*)&C2[(size_t)row * ldc + c0] =
                        __halves2half2(__float2half_rn(v0), __float2half_rn(v1));
                } else if (EPI == 1) {
                    float2 bv = *(const float2*)&bias[c0];
                    float2 r  = *(const float2*)&res[(size_t)row * ldc + c0];
                    *(float2*)&C[(size_t)row * ldc + c0] =
                        make_float2(v0 + bv.x + r.x, v1 + bv.y + r.y);
                } else {
                    float2 bv = *(const float2*)&bias[c0];
                    float a0 = v0 + bv.x;
                    float a1 = v1 + bv.y;
                    float g0 = 0.5f * a0 * (1.0f + erff(a0 * 0.70710678118654752f));
                    float g1 = 0.5f * a1 * (1.0f + erff(a1 * 0.70710678118654752f));
                    *(__half2*)&C2[(size_t)row * ldc + c0] =
                        __halves2half2(__float2half_rn(g0), __float2half_rn(g1));
                }
            }
        }
    }
}

// ============================ weight prep ===================================
// Single: W[K,N] fp32 (layer l at l*K*N) -> out[N][K] fp16, transposed.
__global__ void __launch_bounds__(256) prep_w_single(
    const float* __restrict__ W, int K, int N,
    __half* __restrict__ out, size_t outLayer)
{
    __shared__ float ts[32][33];
    int l  = blockIdx.z;
    const float* Wl = W + (size_t)l * K * N;
    __half* ol = out + (size_t)l * outLayer;
    int k0 = blockIdx.x * 32, n0 = blockIdx.y * 32;
    int tx = threadIdx.x, ty = threadIdx.y;   // 32 x 8
    #pragma unroll
    for (int i = 0; i < 32; i += 8)
        ts[ty + i][tx] = Wl[(size_t)(k0 + ty + i) * N + n0 + tx];
    __syncthreads();
    #pragma unroll
    for (int i = 0; i < 32; i += 8) {
        int n = n0 + ty + i, k = k0 + tx;
        ol[(size_t)n * K + k] = __float2half_rn(ts[tx][ty + i]);
    }
}

// Double: W[K,N] fp32 -> out[N][2K] fp16 [hi|hi] transposed.
__global__ void __launch_bounds__(256) prep_w_double(
    const float* __restrict__ W, int K, int N,
    __half* __restrict__ out, size_t outLayer)
{
    __shared__ float ts[32][33];
    int l  = blockIdx.z;
    const float* Wl = W + (size_t)l * K * N;
    __half* ol = out + (size_t)l * outLayer;
    int k0 = blockIdx.x * 32, n0 = blockIdx.y * 32;
    int tx = threadIdx.x, ty = threadIdx.y;
    #pragma unroll
    for (int i = 0; i < 32; i += 8)
        ts[ty + i][tx] = Wl[(size_t)(k0 + ty + i) * N + n0 + tx];
    __syncthreads();
    #pragma unroll
    for (int i = 0; i < 32; i += 8) {
        int n = n0 + ty + i, k = k0 + tx;
        __half hi = __float2half_rn(ts[tx][ty + i]);
        size_t ro = (size_t)n * (2 * K);
        ol[ro + k]     = hi;
        ol[ro + K + k] = hi;
    }
}

// ---------------- embedding + loss reset ------------------------------------
__global__ void __launch_bounds__(256) embed_kernel(
    const int* __restrict__ ids, const float* __restrict__ tok,
    const float* __restrict__ pos, float* __restrict__ x)
{
    int i = blockIdx.x * 256 + threadIdx.x;
    if (i == 0) g_loss = 0.0f;
    if (i >= MM * DD) return;
    int row = i / DD;
    int d   = i - row * DD;
    int s   = row % SS;
    x[i] = tok[(size_t)ids[row] * DD + d] + pos[(size_t)s * DD + d];
}

// ---------------- LayerNorm core (unbiased std, eps on std) -----------------
__device__ __forceinline__ void ln_stats(const float4& v, int t, float& mean, float& inv)
{
    float s  = v.x + v.y + v.z + v.w;
    float ss = v.x * v.x + v.y * v.y + v.z * v.z + v.w * v.w;
    #pragma unroll
    for (int o = 16; o; o >>= 1) {
        s  += __shfl_xor_sync(0xffffffffu, s,  o);
        ss += __shfl_xor_sync(0xffffffffu, ss, o);
    }
    __shared__ float sh[8];
    int wid = t >> 5, lane = t & 31;
    if (lane == 0) { sh[wid * 2] = s; sh[wid * 2 + 1] = ss; }
    __syncthreads();
    s  = sh[0] + sh[2] + sh[4] + sh[6];
    ss = sh[1] + sh[3] + sh[5] + sh[7];
    mean = s * (1.0f / DD);
    float var = (ss - s * mean) * (1.0f / (DD - 1));
    inv = 1.0f / (sqrtf(fmaxf(var, 0.0f)) + 1e-10f);
}

__global__ void __launch_bounds__(128) ln_kernel(
    const float* __restrict__ x, const float* __restrict__ g,
    const float* __restrict__ b, float* __restrict__ out)
{
    int row = blockIdx.x, t = threadIdx.x;
    float4 v = ((const float4*)(x + (size_t)row * DD))[t];
    float mean, inv;
    ln_stats(v, t, mean, inv);
    float4 gv = ((const float4*)g)[t], bv = ((const float4*)b)[t];
    float4 ov;
    ov.x = (v.x - mean) * inv * gv.x + bv.x;
    ov.y = (v.y - mean) * inv * gv.y + bv.y;
    ov.z = (v.z - mean) * inv * gv.z + bv.z;
    ov.w = (v.w - mean) * inv * gv.w + bv.w;
    ((float4*)(out + (size_t)row * DD))[t] = ov;
}

// LN -> single fp16 [M,512]
__global__ void __launch_bounds__(128) ln_single_kernel(
    const float* __restrict__ x, const float* __restrict__ g,
    const float* __restrict__ b, __half* __restrict__ out)
{
    int row = blockIdx.x, t = threadIdx.x;
    float4 v = ((const float4*)(x + (size_t)row * DD))[t];
    float mean, inv;
    ln_stats(v, t, mean, inv);
    float4 gv = ((const float4*)g)[t], bv = ((const float4*)b)[t];
    size_t ro = (size_t)row * DD + t * 4;
    *(__half2*)&out[ro] = __halves2half2(
        __float2half_rn((v.x - mean) * inv * gv.x + bv.x),
        __float2half_rn((v.y - mean) * inv * gv.y + bv.y));
    *(__half2*)&out[ro + 2] = __halves2half2(
        __float2half_rn((v.z - mean) * inv * gv.z + bv.z),
        __float2half_rn((v.w - mean) * inv * gv.w + bv.w));
}

// LN -> double fp16 [hi|lo], row stride 1024
__global__ void __launch_bounds__(128) ln_double_kernel(
    const float* __restrict__ x, const float* __restrict__ g,
    const float* __restrict__ b, __half* __restrict__ out)
{
    int row = blockIdx.x, t = threadIdx.x;
    float4 v = ((const float4*)(x + (size_t)row * DD))[t];
    float mean, inv;
    ln_stats(v, t, mean, inv);
    float4 gv = ((const float4*)g)[t], bv = ((const float4*)b)[t];
    float o[4] = {
        (v.x - mean) * inv * gv.x + bv.x,
        (v.y - mean) * inv * gv.y + bv.y,
        (v.z - mean) * inv * gv.z + bv.z,
        (v.w - mean) * inv * gv.w + bv.w };
    __half hi[4], lo[4];
    #pragma unroll
    for (int j = 0; j < 4; j++) split_h(o[j], hi[j], lo[j]);
    size_t ro = (size_t)row * K2D + t * 4;
    *(__half2*)&out[ro]          = __halves2half2(hi[0], hi[1]);
    *(__half2*)&out[ro + 2]      = __halves2half2(hi[2], hi[3]);
    *(__half2*)&out[ro + DD]     = __halves2half2(lo[0], lo[1]);
    *(__half2*)&out[ro + DD + 2] = __halves2half2(lo[2], lo[3]);
}

// ---------------- fused causal attention per (b,h) --------------------------
// reads qkv fp16 [M,1536] (q|k|v), writes single-fp16 o [M,512]
__global__ void __launch_bounds__(256) attn_kernel(
    const __half* __restrict__ qkv, __half* __restrict__ oA)
{
    int bh = blockIdx.x;
    int b  = bh >> 3;
    int h  = bh & 7;
    const __half* qb = qkv + (size_t)b * SS * KQKV + h * DHH;
    const __half* kb = qb + DD;
    const __half* vb = qb + 2 * DD;
    __half* ob = oA + (size_t)b * SS * DD + h * DHH;

    __shared__ float Ks[SS][DHH + 1];
    __shared__ float Vs[SS][DHH + 1];
    __shared__ float attn_s[8][SS];

    int tid = threadIdx.x;
    for (int i = tid; i < SS * (DHH / 2); i += 256) {
        int s = i >> 5, e2 = (i & 31) * 2;
        __half2 kk = *(const __half2*)&kb[(size_t)s * KQKV + e2];
        __half2 vv = *(const __half2*)&vb[(size_t)s * KQKV + e2];
        float2 kf = __half22float2(kk), vf = __half22float2(vv);
        Ks[s][e2] = kf.x; Ks[s][e2 + 1] = kf.y;
        Vs[s][e2] = vf.x; Vs[s][e2 + 1] = vf.y;
    }
    __syncthreads();

    int warp = tid >> 5, lane = tid & 31;
    const float scale = 0.044194173824159216f;  // 1/sqrt(512)

    for (int r = 0; r < 8; r++) {
        int s = warp * 8 + r;
        float q0 = __half2float(qb[(size_t)s * KQKV + lane]);
        float q1 = __half2float(qb[(size_t)s * KQKV + lane + 32]);

        float sc0 = 0.0f, sc1 = 0.0f;
        #pragma unroll
        for (int e = 0; e < 32; e++) {
            float qe = __shfl_sync(0xffffffffu, q0, e);
            sc0 = fmaf(qe, Ks[lane][e],      sc0);
            sc1 = fmaf(qe, Ks[lane + 32][e], sc1);
        }
        #pragma unroll
        for (int e = 0; e < 32; e++) {
            float qe = __shfl_sync(0xffffffffu, q1, e);
            sc0 = fmaf(qe, Ks[lane][e + 32],      sc0);
            sc1 = fmaf(qe, Ks[lane + 32][e + 32], sc1);
        }
        sc0 = (lane <= s)      ? sc0 * scale : -1e30f;
        sc1 = (lane + 32 <= s) ? sc1 * scale : -1e30f;

        float m = fmaxf(sc0, sc1);
        #pragma unroll
        for (int off = 16; off; off >>= 1)
            m = fmaxf(m, __shfl_xor_sync(0xffffffffu, m, off));
        float e0 = __expf(sc0 - m), e1 = __expf(sc1 - m);
        float sum = e0 + e1;
        #pragma unroll
        for (int off = 16; off; off >>= 1)
            sum += __shfl_xor_sync(0xffffffffu, sum, off);
        float invs = 1.0f / sum;
        attn_s[warp][lane]      = e0 * invs;
        attn_s[warp][lane + 32] = e1 * invs;
        __syncwarp();

        float o0 = 0.0f, o1 = 0.0f;
        #pragma unroll
        for (int tt = 0; tt < SS; tt++) {
            float a = attn_s[warp][tt];
            o0 = fmaf(a, Vs[tt][lane],      o0);
            o1 = fmaf(a, Vs[tt][lane + 32], o1);
        }
        size_t ro = (size_t)s * DD;
        ob[ro + lane]      = __float2half_rn(o0);
        ob[ro + lane + 32] = __float2half_rn(o1);
        __syncwarp();
    }
}

// ---------------- unembed: 16 rows/block, Wu register-blocked ---------------
#define UROWS 16
__global__ void __launch_bounds__(128) unembed_kernel(
    const float* __restrict__ x, const float* __restrict__ Wu,
    const float* __restrict__ bu, float* __restrict__ logits)
{
    __shared__ float xs[UROWS][DD];
    int r0 = blockIdx.x * UROWS;
    const float4* src = (const float4*)(x + (size_t)r0 * DD);
    float4* dst = (float4*)&xs[0][0];
    for (int i = threadIdx.x; i < UROWS * DD / 4; i += 128)
        dst[i] = src[i];
    __syncthreads();
    int c = threadIdx.x;
    if (c < VV) {
        float acc[UROWS];
        float bc = bu[c];
        #pragma unroll
        for (int r = 0; r < UROWS; r++) acc[r] = bc;
        #pragma unroll 4
        for (int k = 0; k < DD; k++) {
            float w = Wu[(size_t)k * VV + c];
            #pragma unroll
            for (int r = 0; r < UROWS; r++)
                acc[r] = fmaf(xs[r][k], w, acc[r]);
        }
        #pragma unroll
        for (int r = 0; r < UROWS; r++)
            logits[(size_t)(r0 + r) * VV + c] = acc[r];
    }
}

// ---------------- cross-entropy loss ----------------------------------------
__global__ void __launch_bounds__(128) loss_kernel(
    const float* __restrict__ logits, const int* __restrict__ tgt)
{
    int warp = threadIdx.x >> 5, lane = threadIdx.x & 31;
    int row  = blockIdx.x * 4 + warp;
    const float* lr = logits + (size_t)row * VV;

    float l0 = lr[lane];
    float l1 = lr[lane + 32];
    float l2 = (lane + 64 < VV) ? lr[lane + 64] : -1e30f;

    float m = fmaxf(fmaxf(l0, l1), l2);
    #pragma unroll
    for (int off = 16; off; off >>= 1)
        m = fmaxf(m, __shfl_xor_sync(0xffffffffu, m, off));
    float sum = expf(l0 - m) + expf(l1 - m) + ((lane + 64 < VV) ? expf(l2 - m) : 0.0f);
    #pragma unroll
    for (int off = 16; off; off >>= 1)
        sum += __shfl_xor_sync(0xffffffffu, sum, off);

    if (lane == 0) {
        float lse = m + logf(sum);
        float lt  = lr[tgt[row]];
        atomicAdd(&g_loss, lse - lt);
    }
}

// ---------------- output assembly -------------------------------------------
__global__ void __launch_bounds__(256) copy_out_kernel(
    const float* __restrict__ lg, float* __restrict__ out, int n)
{
    int i = blockIdx.x * 256 + threadIdx.x;
    if (i < n) out[i] = lg[i];
}
__global__ void __launch_bounds__(128) write_loss_kernel(
    float* __restrict__ out, int lo, int hi)
{
    int i = lo + blockIdx.x * 128 + threadIdx.x;
    if (i < hi) out[i] = g_loss * (1.0f / (float)MM);
}

// ---------------- launcher ----------------------------------------------------
#define GSMEM (STG * 49152)

extern "C" void kernel_launch(void* const* d_in, const int* in_sizes, int n_in,
                              void* d_out, int out_size)
{
    const int*   ids  = (const int*)d_in[0];
    const int*   tgt  = (const int*)d_in[1];
    const float* tok  = (const float*)d_in[2];
    const float* pos  = (const float*)d_in[3];
    const float* Wq   = (const float*)d_in[4];
    const float* Wk   = (const float*)d_in[5];
    const float* Wv   = (const float*)d_in[6];
    const float* Wo   = (const float*)d_in[7];
    const float* bo   = (const float*)d_in[8];
    const float* W1   = (const float*)d_in[9];
    const float* b1   = (const float*)d_in[10];
    const float* W2   = (const float*)d_in[11];
    const float* b2   = (const float*)d_in[12];
    const float* ln1g = (const float*)d_in[13];
    const float* ln1b = (const float*)d_in[14];
    const float* ln2g = (const float*)d_in[15];
    const float* ln2b = (const float*)d_in[16];
    const float* lnfg = (const float*)d_in[17];
    const float* lnfb = (const float*)d_in[18];
    const float* Wu   = (const float*)d_in[19];
    const float* bu   = (const float*)d_in[20];
    float* out = (float*)d_out;

    float *x, *h, *lg;
    __half *qkv, *hA1, *hA2, *oA, *hidA, *Wqkv, *WoT, *W1T, *W2T;
    cudaGetSymbolAddress((void**)&x,    g_x);
    cudaGetSymbolAddress((void**)&h,    g_h);
    cudaGetSymbolAddress((void**)&qkv,  g_qkv);
    cudaGetSymbolAddress((void**)&hA1,  g_hA1);
    cudaGetSymbolAddress((void**)&hA2,  g_hA2);
    cudaGetSymbolAddress((void**)&oA,   g_oA);
    cudaGetSymbolAddress((void**)&hidA, g_hidA);
    cudaGetSymbolAddress((void**)&lg,   g_logits);
    cudaGetSymbolAddress((void**)&Wqkv, g_Wqkv);
    cudaGetSymbolAddress((void**)&WoT,  g_WoT);
    cudaGetSymbolAddress((void**)&W1T,  g_W1T);
    cudaGetSymbolAddress((void**)&W2T,  g_W2T);

    cudaFuncSetAttribute(gemm_mma<0>, cudaFuncAttributeMaxDynamicSharedMemorySize, GSMEM);
    cudaFuncSetAttribute(gemm_mma<1>, cudaFuncAttributeMaxDynamicSharedMemorySize, GSMEM);
    cudaFuncSetAttribute(gemm_mma<2>, cudaFuncAttributeMaxDynamicSharedMemorySize, GSMEM);

    int nlog = MM * VV;
    float* logits_dst = (out_size >= nlog) ? out : lg;

    // ---- weight prep: 6 launches (grid.z = layer) ----
    dim3 pb(32, 8);
    prep_w_single<<<dim3(DD/32, DD/32, LL), pb>>>(Wq, DD, DD,
        Wqkv,                       (size_t)KQKV * DD);
    prep_w_single<<<dim3(DD/32, DD/32, LL), pb>>>(Wk, DD, DD,
        Wqkv + (size_t)DD * DD,     (size_t)KQKV * DD);
    prep_w_single<<<dim3(DD/32, DD/32, LL), pb>>>(Wv, DD, DD,
        Wqkv + (size_t)2 * DD * DD, (size_t)KQKV * DD);
    prep_w_single<<<dim3(DD/32, DD/32, LL), pb>>>(Wo, DD, DD,
        WoT,  (size_t)DD * DD);
    prep_w_double<<<dim3(DD/32, DFF/32, LL), pb>>>(W1, DD, DFF,
        W1T,  (size_t)DFF * K2D);
    prep_w_single<<<dim3(DFF/32, DD/32, LL), pb>>>(W2, DFF, DD,
        W2T,  (size_t)DD * DFF);

    embed_kernel<<<(MM * DD + 255) / 256, 256>>>(ids, tok, pos, x);

    for (int l = 0; l < LL; l++) {
        ln_single_kernel<<<MM, 128>>>(x, ln1g + l * DD, ln1b + l * DD, hA1);

        // qkv(fp16) = hA1 @ Wqkv^T   single fp16, K=512
        gemm_mma<0><<<dim3(KQKV/256, MM/128), 256, GSMEM>>>(
            hA1, DD, Wqkv + (size_t)l*KQKV*DD, DD, DD,
            nullptr, qkv, KQKV, nullptr, nullptr);

        attn_kernel<<<BB * HH, 256>>>(qkv, oA);

        // x = x + o @ Wo + bo    single fp16, K=512
        gemm_mma<1><<<dim3(DD/256, MM/128), 256, GSMEM>>>(
            oA, DD, WoT + (size_t)l*DD*DD, DD, DD,
            x, nullptr, DD, bo + l * DD, x);

        ln_double_kernel<<<MM, 128>>>(x, ln2g + l * DD, ln2b + l * DD, hA2);

        // hidA(fp16) = gelu(hA2 @ W1^T + b1)   double, K=1024
        gemm_mma<2><<<dim3(DFF/256, MM/128), 256, GSMEM>>>(
            hA2, K2D, W1T + (size_t)l*DFF*K2D, K2D, K2D,
            nullptr, hidA, DFF, b1 + l * DFF, nullptr);

        // x = x + hid @ W2 + b2   single, K=2048
        gemm_mma<1><<<dim3(DD/256, MM/128), 256, GSMEM>>>(
            hidA, DFF, W2T + (size_t)l*DD*DFF, DFF, DFF,
            x, nullptr, DD, b2 + l * DD, x);
    }

    ln_kernel<<<MM, 128>>>(x, lnfg, lnfb, h);
    unembed_kernel<<<MM / UROWS, 128>>>(h, Wu, bu, logits_dst);
    loss_kernel<<<MM / 4, 128>>>(logits_dst, tgt);

    if (logits_dst != out) {
        int ncopy = out_size < nlog ? out_size : nlog;
        if (ncopy > 0)
            copy_out_kernel<<<(ncopy + 255) / 256, 256>>>(lg, out, ncopy);
    }
    if (out_size > nlog) {
        int tail = out_size - nlog;
        write_loss_kernel<<<(tail + 127) / 128, 128>>>(out, nlog, out_size);
    }
}

// round 8
// speedup vs baseline: 2.9346x; 1.5321x over previous
#include <cuda_runtime.h>
#include <cuda_fp16.h>
#include <math.h>
#include <stdint.h>

// Problem constants
#define LL   8
#define DD   512
#define HH   8
#define DHH  64
#define SS   64
#define VV   66
#define BB   256
#define MM   (BB * SS)      // 16384 token rows
#define DFF  (4 * DD)       // 2048
#define KQKV (3 * DD)       // 1536

// ---------------- scratch (static device allocations; no cudaMalloc) -------
__device__ float g_x[(size_t)MM * DD];
__device__ float g_h[(size_t)MM * DD];
__device__ __half g_qkv[(size_t)MM * KQKV];      // fp16 qkv [M, 1536]
__device__ __half g_hA1[(size_t)MM * DD];        // single-fp16 LN out
__device__ __half g_oA[(size_t)MM * DD];         // single-fp16 attn out
__device__ __half g_hidA[(size_t)MM * DFF];      // single-fp16 gelu out
__device__ float g_logits[(size_t)MM * VV];
__device__ float g_loss;

// fp16 transposed weights (all single)
__device__ __half g_Wqkv[(size_t)LL * KQKV * DD];   // [1536][512]
__device__ __half g_WoT [(size_t)LL * DD * DD];     // [512][512]
__device__ __half g_W1T [(size_t)LL * DFF * DD];    // [2048][512]
__device__ __half g_W2T [(size_t)LL * DD * DFF];    // [512][2048]

// ============================ PTX helpers ===================================
__device__ __forceinline__ uint32_t smem_u32(const void* p) {
    uint32_t a;
    asm("{ .reg .u64 t; cvta.to.shared.u64 t, %1; cvt.u32.u64 %0, t; }"
        : "=r"(a) : "l"(p));
    return a;
}
__device__ __forceinline__ void cp16(uint32_t s, const void* g) {
    asm volatile("cp.async.cg.shared.global [%0], [%1], 16;" :: "r"(s), "l"(g));
}
__device__ __forceinline__ void cp_commit() {
    asm volatile("cp.async.commit_group;" ::: "memory");
}
template<int N>
__device__ __forceinline__ void cp_wait() {
    asm volatile("cp.async.wait_group %0;" :: "n"(N) : "memory");
}
__device__ __forceinline__ void ldsm4(uint32_t* r, uint32_t addr) {
    asm volatile("ldmatrix.sync.aligned.m8n8.x4.shared.b16 {%0,%1,%2,%3}, [%4];"
        : "=r"(r[0]), "=r"(r[1]), "=r"(r[2]), "=r"(r[3]) : "r"(addr));
}
__device__ __forceinline__ void ldsm4t(uint32_t* r, uint32_t addr) {
    asm volatile("ldmatrix.sync.aligned.m8n8.x4.trans.shared.b16 {%0,%1,%2,%3}, [%4];"
        : "=r"(r[0]), "=r"(r[1]), "=r"(r[2]), "=r"(r[3]) : "r"(addr));
}
__device__ __forceinline__ void mma16816(float* d, const uint32_t* a, uint32_t b0, uint32_t b1) {
    asm volatile(
        "mma.sync.aligned.m16n8k16.row.col.f32.f16.f16.f32 "
        "{%0,%1,%2,%3}, {%4,%5,%6,%7}, {%8,%9}, {%0,%1,%2,%3};"
        : "+f"(d[0]), "+f"(d[1]), "+f"(d[2]), "+f"(d[3])
        : "r"(a[0]), "r"(a[1]), "r"(a[2]), "r"(a[3]), "r"(b0), "r"(b1));
}
__device__ __forceinline__ uint32_t pack_h2(float x, float y) {
    __half2 h = __halves2half2(__float2half_rn(x), __float2half_rn(y));
    return *(uint32_t*)&h;
}

// ============================ HMMA GEMM =====================================
// C[M,N] = A[M,K3] @ B[N,K3]^T, fp16 K-major.
// CTA tile 128x256, BK=64, 3-stage cp.async pipeline, 8 warps 2m x 4n, 64x64 each.
// EPI 0: C2 fp16 = acc
// EPI 1: C fp32 = acc + bias + res  (res==C aliasing ok)
// EPI 2: C2 fp16 = gelu(acc + bias)
#define STG       3
#define STG_BYTES 49152u

template<int EPI>
__global__ void __launch_bounds__(256, 1)
gemm_mma(const __half* __restrict__ A, int lda,
         const __half* __restrict__ B, int ldb,
         int K3,
         float* __restrict__ C, __half* __restrict__ C2, int ldc,
         const float* __restrict__ bias,
         float* __restrict__ res)
{
    extern __shared__ char smem[];
    const int t    = threadIdx.x;
    const int wid  = t >> 5, lane = t & 31;
    const int brow = blockIdx.y * 128;
    const int bcol = blockIdx.x * 256;
    const int wm   = (wid & 1) * 64;
    const int wn   = (wid >> 1) * 64;

    uint32_t sbase = smem_u32(smem);

    float acc[4][8][4];
    #pragma unroll
    for (int i = 0; i < 4; i++)
        #pragma unroll
        for (int j = 0; j < 8; j++)
            #pragma unroll
            for (int e = 0; e < 4; e++) acc[i][j][e] = 0.0f;

    auto load_stage = [&](int s) {
        int buf = s % STG;
        int k0  = s << 6;
        uint32_t sa = sbase + buf * STG_BYTES;
        uint32_t sb = sa + 16384u;
        #pragma unroll
        for (int i = 0; i < 4; i++) {
            int c   = t + (i << 8);
            int row = c >> 3;
            int c16 = c & 7;
            uint32_t off = (uint32_t)(row * 128 + c16 * 16);
            off ^= (off >> 3) & 0x70u;
            cp16(sa + off, A + (size_t)(brow + row) * lda + k0 + c16 * 8);
        }
        #pragma unroll
        for (int i = 0; i < 8; i++) {
            int c   = t + (i << 8);
            int row = c >> 3;
            int c16 = c & 7;
            uint32_t off = (uint32_t)(row * 128 + c16 * 16);
            off ^= (off >> 3) & 0x70u;
            cp16(sb + off, B + (size_t)(bcol + row) * ldb + k0 + c16 * 8);
        }
        cp_commit();
    };

    const int S = K3 >> 6;

    const int lrow = ((lane >> 3) & 1) * 8 + (lane & 7);
    const int lkb  = (lane >> 4) * 16;

    load_stage(0);
    load_stage(1);

    for (int s = 0; s < S; s++) {
        int buf = s % STG;
        cp_wait<1>();
        __syncthreads();

        uint32_t sa = sbase + buf * STG_BYTES;
        uint32_t sb = sa + 16384u;

        #pragma unroll
        for (int kk = 0; kk < 4; kk++) {
            int kbyte = kk * 32 + lkb;

            uint32_t afr[4][4];
            #pragma unroll
            for (int mi = 0; mi < 4; mi++) {
                uint32_t off = (uint32_t)((wm + mi * 16 + lrow) * 128 + kbyte);
                off ^= (off >> 3) & 0x70u;
                ldsm4(afr[mi], sa + off);
            }
            uint32_t bfr[4][4];
            #pragma unroll
            for (int nj = 0; nj < 4; nj++) {
                uint32_t off = (uint32_t)((wn + nj * 16 + lrow) * 128 + kbyte);
                off ^= (off >> 3) & 0x70u;
                ldsm4(bfr[nj], sb + off);
            }
            #pragma unroll
            for (int mi = 0; mi < 4; mi++) {
                #pragma unroll
                for (int nj = 0; nj < 4; nj++) {
                    mma16816(acc[mi][2 * nj],     afr[mi], bfr[nj][0], bfr[nj][2]);
                    mma16816(acc[mi][2 * nj + 1], afr[mi], bfr[nj][1], bfr[nj][3]);
                }
            }
        }
        __syncthreads();
        if (s + 2 < S) load_stage(s + 2);
    }

    #pragma unroll
    for (int mi = 0; mi < 4; mi++) {
        #pragma unroll
        for (int ni = 0; ni < 8; ni++) {
            int r0 = brow + wm + mi * 16 + (lane >> 2);
            int c0 = bcol + wn + ni * 8 + ((lane & 3) << 1);
            #pragma unroll
            for (int half = 0; half < 2; half++) {
                int row = r0 + half * 8;
                float v0 = acc[mi][ni][half * 2];
                float v1 = acc[mi][ni][half * 2 + 1];
                if (EPI == 0) {
                    *(uint32_t*)&C2[(size_t)row * ldc + c0] = pack_h2(v0, v1);
                } else if (EPI == 1) {
                    float2 bv = *(const float2*)&bias[c0];
                    float2 r  = *(const float2*)&res[(size_t)row * ldc + c0];
                    *(float2*)&C[(size_t)row * ldc + c0] =
                        make_float2(v0 + bv.x + r.x, v1 + bv.y + r.y);
                } else {
                    float2 bv = *(const float2*)&bias[c0];
                    float a0 = v0 + bv.x;
                    float a1 = v1 + bv.y;
                    float g0 = 0.5f * a0 * (1.0f + erff(a0 * 0.70710678118654752f));
                    float g1 = 0.5f * a1 * (1.0f + erff(a1 * 0.70710678118654752f));
                    *(uint32_t*)&C2[(size_t)row * ldc + c0] = pack_h2(g0, g1);
                }
            }
        }
    }
}

// ============================ weight prep ===================================
__global__ void __launch_bounds__(256) prep_w_single(
    const float* __restrict__ W, int K, int N,
    __half* __restrict__ out, size_t outLayer)
{
    __shared__ float ts[32][33];
    int l  = blockIdx.z;
    const float* Wl = W + (size_t)l * K * N;
    __half* ol = out + (size_t)l * outLayer;
    int k0 = blockIdx.x * 32, n0 = blockIdx.y * 32;
    int tx = threadIdx.x, ty = threadIdx.y;   // 32 x 8
    #pragma unroll
    for (int i = 0; i < 32; i += 8)
        ts[ty + i][tx] = Wl[(size_t)(k0 + ty + i) * N + n0 + tx];
    __syncthreads();
    #pragma unroll
    for (int i = 0; i < 32; i += 8) {
        int n = n0 + ty + i, k = k0 + tx;
        ol[(size_t)n * K + k] = __float2half_rn(ts[tx][ty + i]);
    }
}

// ---------------- embedding + loss reset ------------------------------------
__global__ void __launch_bounds__(256) embed_kernel(
    const int* __restrict__ ids, const float* __restrict__ tok,
    const float* __restrict__ pos, float* __restrict__ x)
{
    int i = blockIdx.x * 256 + threadIdx.x;
    if (i == 0) g_loss = 0.0f;
    if (i >= MM * DD) return;
    int row = i / DD;
    int d   = i - row * DD;
    int s   = row % SS;
    x[i] = tok[(size_t)ids[row] * DD + d] + pos[(size_t)s * DD + d];
}

// ---------------- LayerNorm core (unbiased std, eps on std) -----------------
__device__ __forceinline__ void ln_stats(const float4& v, int t, float& mean, float& inv)
{
    float s  = v.x + v.y + v.z + v.w;
    float ss = v.x * v.x + v.y * v.y + v.z * v.z + v.w * v.w;
    #pragma unroll
    for (int o = 16; o; o >>= 1) {
        s  += __shfl_xor_sync(0xffffffffu, s,  o);
        ss += __shfl_xor_sync(0xffffffffu, ss, o);
    }
    __shared__ float sh[8];
    int wid = t >> 5, lane = t & 31;
    if (lane == 0) { sh[wid * 2] = s; sh[wid * 2 + 1] = ss; }
    __syncthreads();
    s  = sh[0] + sh[2] + sh[4] + sh[6];
    ss = sh[1] + sh[3] + sh[5] + sh[7];
    mean = s * (1.0f / DD);
    float var = (ss - s * mean) * (1.0f / (DD - 1));
    inv = 1.0f / (sqrtf(fmaxf(var, 0.0f)) + 1e-10f);
}

__global__ void __launch_bounds__(128) ln_kernel(
    const float* __restrict__ x, const float* __restrict__ g,
    const float* __restrict__ b, float* __restrict__ out)
{
    int row = blockIdx.x, t = threadIdx.x;
    float4 v = ((const float4*)(x + (size_t)row * DD))[t];
    float mean, inv;
    ln_stats(v, t, mean, inv);
    float4 gv = ((const float4*)g)[t], bv = ((const float4*)b)[t];
    float4 ov;
    ov.x = (v.x - mean) * inv * gv.x + bv.x;
    ov.y = (v.y - mean) * inv * gv.y + bv.y;
    ov.z = (v.z - mean) * inv * gv.z + bv.z;
    ov.w = (v.w - mean) * inv * gv.w + bv.w;
    ((float4*)(out + (size_t)row * DD))[t] = ov;
}

// LN -> single fp16 [M,512]
__global__ void __launch_bounds__(128) ln_single_kernel(
    const float* __restrict__ x, const float* __restrict__ g,
    const float* __restrict__ b, __half* __restrict__ out)
{
    int row = blockIdx.x, t = threadIdx.x;
    float4 v = ((const float4*)(x + (size_t)row * DD))[t];
    float mean, inv;
    ln_stats(v, t, mean, inv);
    float4 gv = ((const float4*)g)[t], bv = ((const float4*)b)[t];
    size_t ro = (size_t)row * DD + t * 4;
    *(uint32_t*)&out[ro]     = pack_h2((v.x - mean) * inv * gv.x + bv.x,
                                       (v.y - mean) * inv * gv.y + bv.y);
    *(uint32_t*)&out[ro + 2] = pack_h2((v.z - mean) * inv * gv.z + bv.z,
                                       (v.w - mean) * inv * gv.w + bv.w);
}

// ---------------- MMA causal attention per (b,h) -----------------------------
// qkv fp16 [M,1536] (q|k|v) -> oA fp16 [M,512]
// Block: 128 threads (4 warps), warp w handles 16 query rows [16w, 16w+16).
__global__ void __launch_bounds__(128) attn_mma_kernel(
    const __half* __restrict__ qkv, __half* __restrict__ oA)
{
    __shared__ __align__(16) char smem[3 * 8192];  // q,k,v tiles 64x128B SW128

    int bh = blockIdx.x;
    int b  = bh >> 3;
    int h  = bh & 7;
    const __half* qb = qkv + (size_t)b * SS * KQKV + h * DHH;
    const __half* kb = qb + DD;
    const __half* vb = qb + 2 * DD;
    __half* ob = oA + (size_t)b * SS * DD + h * DHH;

    uint32_t sq = smem_u32(smem);
    uint32_t sk = sq + 8192u;
    uint32_t sv = sq + 16384u;

    int t = threadIdx.x, wid = t >> 5, lane = t & 31;

    // load q,k,v tiles: 512 cp16 each
    for (int i = t; i < 512; i += 128) {
        int row = i >> 3, c = i & 7;
        uint32_t off = (uint32_t)(row * 128 + c * 16);
        off ^= (off >> 3) & 0x70u;
        const size_t go = (size_t)row * KQKV + c * 8;
        cp16(sq + off, qb + go);
        cp16(sk + off, kb + go);
        cp16(sv + off, vb + go);
    }
    cp_commit();
    cp_wait<0>();
    __syncthreads();

    const int m0   = wid * 16;
    const int lrow = ((lane >> 3) & 1) * 8 + (lane & 7);
    const int lkb  = (lane >> 4) * 16;

    // ---- scores S = q @ k^T  (fp32 accum) ----
    float sc[8][4];
    #pragma unroll
    for (int i = 0; i < 8; i++)
        #pragma unroll
        for (int e = 0; e < 4; e++) sc[i][e] = 0.0f;

    #pragma unroll
    for (int kk = 0; kk < 4; kk++) {
        int kbyte = kk * 32 + lkb;
        uint32_t aoff = (uint32_t)((m0 + lrow) * 128 + kbyte);
        aoff ^= (aoff >> 3) & 0x70u;
        uint32_t afr[4];
        ldsm4(afr, sq + aoff);
        #pragma unroll
        for (int nj = 0; nj < 4; nj++) {
            uint32_t boff = (uint32_t)((nj * 16 + lrow) * 128 + kbyte);
            boff ^= (boff >> 3) & 0x70u;
            uint32_t bfr[4];
            ldsm4(bfr, sk + boff);
            mma16816(sc[2 * nj],     afr, bfr[0], bfr[2]);
            mma16816(sc[2 * nj + 1], afr, bfr[1], bfr[3]);
        }
    }

    // ---- masked softmax (rows r_lo = m0+(lane>>2), r_hi = r_lo+8) ----
    const float scale = 0.044194173824159216f;  // 1/sqrt(512)
    int r_lo = m0 + (lane >> 2);
    int r_hi = r_lo + 8;
    float mx0 = -1e30f, mx1 = -1e30f;
    #pragma unroll
    for (int nt = 0; nt < 8; nt++) {
        int c0 = nt * 8 + ((lane & 3) << 1);
        sc[nt][0] = (c0     <= r_lo) ? sc[nt][0] * scale : -1e30f;
        sc[nt][1] = (c0 + 1 <= r_lo) ? sc[nt][1] * scale : -1e30f;
        sc[nt][2] = (c0     <= r_hi) ? sc[nt][2] * scale : -1e30f;
        sc[nt][3] = (c0 + 1 <= r_hi) ? sc[nt][3] * scale : -1e30f;
        mx0 = fmaxf(mx0, fmaxf(sc[nt][0], sc[nt][1]));
        mx1 = fmaxf(mx1, fmaxf(sc[nt][2], sc[nt][3]));
    }
    mx0 = fmaxf(mx0, __shfl_xor_sync(0xffffffffu, mx0, 1));
    mx0 = fmaxf(mx0, __shfl_xor_sync(0xffffffffu, mx0, 2));
    mx1 = fmaxf(mx1, __shfl_xor_sync(0xffffffffu, mx1, 1));
    mx1 = fmaxf(mx1, __shfl_xor_sync(0xffffffffu, mx1, 2));

    float sum0 = 0.0f, sum1 = 0.0f;
    #pragma unroll
    for (int nt = 0; nt < 8; nt++) {
        sc[nt][0] = __expf(sc[nt][0] - mx0);
        sc[nt][1] = __expf(sc[nt][1] - mx0);
        sc[nt][2] = __expf(sc[nt][2] - mx1);
        sc[nt][3] = __expf(sc[nt][3] - mx1);
        sum0 += sc[nt][0] + sc[nt][1];
        sum1 += sc[nt][2] + sc[nt][3];
    }
    sum0 += __shfl_xor_sync(0xffffffffu, sum0, 1);
    sum0 += __shfl_xor_sync(0xffffffffu, sum0, 2);
    sum1 += __shfl_xor_sync(0xffffffffu, sum1, 1);
    sum1 += __shfl_xor_sync(0xffffffffu, sum1, 2);
    float inv0 = 1.0f / sum0, inv1 = 1.0f / sum1;

    // ---- O = P @ V ----
    float oacc[8][4];
    #pragma unroll
    for (int i = 0; i < 8; i++)
        #pragma unroll
        for (int e = 0; e < 4; e++) oacc[i][e] = 0.0f;

    int jrow = lane & 15;
    int echunk = (lane >> 4) * 16;
    #pragma unroll
    for (int kk = 0; kk < 4; kk++) {
        // P fragments from score C-frag layout (free conversion)
        uint32_t afr[4];
        afr[0] = pack_h2(sc[2 * kk][0] * inv0,     sc[2 * kk][1] * inv0);
        afr[1] = pack_h2(sc[2 * kk][2] * inv1,     sc[2 * kk][3] * inv1);
        afr[2] = pack_h2(sc[2 * kk + 1][0] * inv0, sc[2 * kk + 1][1] * inv0);
        afr[3] = pack_h2(sc[2 * kk + 1][2] * inv1, sc[2 * kk + 1][3] * inv1);

        #pragma unroll
        for (int ne = 0; ne < 4; ne++) {
            uint32_t boff = (uint32_t)((kk * 16 + jrow) * 128 + ne * 32 + echunk);
            boff ^= (boff >> 3) & 0x70u;
            uint32_t bfr[4];
            ldsm4t(bfr, sv + boff);
            mma16816(oacc[2 * ne],     afr, bfr[0], bfr[1]);
            mma16816(oacc[2 * ne + 1], afr, bfr[2], bfr[3]);
        }
    }

    // ---- store O (fp16) ----
    #pragma unroll
    for (int nt = 0; nt < 8; nt++) {
        int e = nt * 8 + ((lane & 3) << 1);
        *(uint32_t*)&ob[(size_t)r_lo * DD + e] = pack_h2(oacc[nt][0], oacc[nt][1]);
        *(uint32_t*)&ob[(size_t)r_hi * DD + e] = pack_h2(oacc[nt][2], oacc[nt][3]);
    }
}

// ---------------- unembed: 16 rows/block, Wu register-blocked ---------------
#define UROWS 16
__global__ void __launch_bounds__(128) unembed_kernel(
    const float* __restrict__ x, const float* __restrict__ Wu,
    const float* __restrict__ bu, float* __restrict__ logits)
{
    __shared__ float xs[UROWS][DD];
    int r0 = blockIdx.x * UROWS;
    const float4* src = (const float4*)(x + (size_t)r0 * DD);
    float4* dst = (float4*)&xs[0][0];
    for (int i = threadIdx.x; i < UROWS * DD / 4; i += 128)
        dst[i] = src[i];
    __syncthreads();
    int c = threadIdx.x;
    if (c < VV) {
        float acc[UROWS];
        float bc = bu[c];
        #pragma unroll
        for (int r = 0; r < UROWS; r++) acc[r] = bc;
        #pragma unroll 4
        for (int k = 0; k < DD; k++) {
            float w = Wu[(size_t)k * VV + c];
            #pragma unroll
            for (int r = 0; r < UROWS; r++)
                acc[r] = fmaf(xs[r][k], w, acc[r]);
        }
        #pragma unroll
        for (int r = 0; r < UROWS; r++)
            logits[(size_t)(r0 + r) * VV + c] = acc[r];
    }
}

// ---------------- cross-entropy loss ----------------------------------------
__global__ void __launch_bounds__(128) loss_kernel(
    const float* __restrict__ logits, const int* __restrict__ tgt)
{
    int warp = threadIdx.x >> 5, lane = threadIdx.x & 31;
    int row  = blockIdx.x * 4 + warp;
    const float* lr = logits + (size_t)row * VV;

    float l0 = lr[lane];
    float l1 = lr[lane + 32];
    float l2 = (lane + 64 < VV) ? lr[lane + 64] : -1e30f;

    float m = fmaxf(fmaxf(l0, l1), l2);
    #pragma unroll
    for (int off = 16; off; off >>= 1)
        m = fmaxf(m, __shfl_xor_sync(0xffffffffu, m, off));
    float sum = expf(l0 - m) + expf(l1 - m) + ((lane + 64 < VV) ? expf(l2 - m) : 0.0f);
    #pragma unroll
    for (int off = 16; off; off >>= 1)
        sum += __shfl_xor_sync(0xffffffffu, sum, off);

    if (lane == 0) {
        float lse = m + logf(sum);
        float lt  = lr[tgt[row]];
        atomicAdd(&g_loss, lse - lt);
    }
}

// ---------------- output assembly -------------------------------------------
__global__ void __launch_bounds__(256) copy_out_kernel(
    const float* __restrict__ lg, float* __restrict__ out, int n)
{
    int i = blockIdx.x * 256 + threadIdx.x;
    if (i < n) out[i] = lg[i];
}
__global__ void __launch_bounds__(128) write_loss_kernel(
    float* __restrict__ out, int lo, int hi)
{
    int i = lo + blockIdx.x * 128 + threadIdx.x;
    if (i < hi) out[i] = g_loss * (1.0f / (float)MM);
}

// ---------------- launcher ----------------------------------------------------
#define GSMEM (STG * 49152)

extern "C" void kernel_launch(void* const* d_in, const int* in_sizes, int n_in,
                              void* d_out, int out_size)
{
    const int*   ids  = (const int*)d_in[0];
    const int*   tgt  = (const int*)d_in[1];
    const float* tok  = (const float*)d_in[2];
    const float* pos  = (const float*)d_in[3];
    const float* Wq   = (const float*)d_in[4];
    const float* Wk   = (const float*)d_in[5];
    const float* Wv   = (const float*)d_in[6];
    const float* Wo   = (const float*)d_in[7];
    const float* bo   = (const float*)d_in[8];
    const float* W1   = (const float*)d_in[9];
    const float* b1   = (const float*)d_in[10];
    const float* W2   = (const float*)d_in[11];
    const float* b2   = (const float*)d_in[12];
    const float* ln1g = (const float*)d_in[13];
    const float* ln1b = (const float*)d_in[14];
    const float* ln2g = (const float*)d_in[15];
    const float* ln2b = (const float*)d_in[16];
    const float* lnfg = (const float*)d_in[17];
    const float* lnfb = (const float*)d_in[18];
    const float* Wu   = (const float*)d_in[19];
    const float* bu   = (const float*)d_in[20];
    float* out = (float*)d_out;

    float *x, *h, *lg;
    __half *qkv, *hA1, *oA, *hidA, *Wqkv, *WoT, *W1T, *W2T;
    cudaGetSymbolAddress((void**)&x,    g_x);
    cudaGetSymbolAddress((void**)&h,    g_h);
    cudaGetSymbolAddress((void**)&qkv,  g_qkv);
    cudaGetSymbolAddress((void**)&hA1,  g_hA1);
    cudaGetSymbolAddress((void**)&oA,   g_oA);
    cudaGetSymbolAddress((void**)&hidA, g_hidA);
    cudaGetSymbolAddress((void**)&lg,   g_logits);
    cudaGetSymbolAddress((void**)&Wqkv, g_Wqkv);
    cudaGetSymbolAddress((void**)&WoT,  g_WoT);
    cudaGetSymbolAddress((void**)&W1T,  g_W1T);
    cudaGetSymbolAddress((void**)&W2T,  g_W2T);

    cudaFuncSetAttribute(gemm_mma<0>, cudaFuncAttributeMaxDynamicSharedMemorySize, GSMEM);
    cudaFuncSetAttribute(gemm_mma<1>, cudaFuncAttributeMaxDynamicSharedMemorySize, GSMEM);
    cudaFuncSetAttribute(gemm_mma<2>, cudaFuncAttributeMaxDynamicSharedMemorySize, GSMEM);

    int nlog = MM * VV;
    float* logits_dst = (out_size >= nlog) ? out : lg;

    // ---- weight prep: 6 launches (grid.z = layer) ----
    dim3 pb(32, 8);
    prep_w_single<<<dim3(DD/32, DD/32, LL), pb>>>(Wq, DD, DD,
        Wqkv,                       (size_t)KQKV * DD);
    prep_w_single<<<dim3(DD/32, DD/32, LL), pb>>>(Wk, DD, DD,
        Wqkv + (size_t)DD * DD,     (size_t)KQKV * DD);
    prep_w_single<<<dim3(DD/32, DD/32, LL), pb>>>(Wv, DD, DD,
        Wqkv + (size_t)2 * DD * DD, (size_t)KQKV * DD);
    prep_w_single<<<dim3(DD/32, DD/32, LL), pb>>>(Wo, DD, DD,
        WoT,  (size_t)DD * DD);
    prep_w_single<<<dim3(DD/32, DFF/32, LL), pb>>>(W1, DD, DFF,
        W1T,  (size_t)DFF * DD);
    prep_w_single<<<dim3(DFF/32, DD/32, LL), pb>>>(W2, DFF, DD,
        W2T,  (size_t)DD * DFF);

    embed_kernel<<<(MM * DD + 255) / 256, 256>>>(ids, tok, pos, x);

    for (int l = 0; l < LL; l++) {
        ln_single_kernel<<<MM, 128>>>(x, ln1g + l * DD, ln1b + l * DD, hA1);

        // qkv(fp16) = hA1 @ Wqkv^T   K=512
        gemm_mma<0><<<dim3(KQKV/256, MM/128), 256, GSMEM>>>(
            hA1, DD, Wqkv + (size_t)l*KQKV*DD, DD, DD,
            nullptr, qkv, KQKV, nullptr, nullptr);

        attn_mma_kernel<<<BB * HH, 128>>>(qkv, oA);

        // x = x + o @ Wo + bo    K=512
        gemm_mma<1><<<dim3(DD/256, MM/128), 256, GSMEM>>>(
            oA, DD, WoT + (size_t)l*DD*DD, DD, DD,
            x, nullptr, DD, bo + l * DD, x);

        ln_single_kernel<<<MM, 128>>>(x, ln2g + l * DD, ln2b + l * DD, hA1);

        // hidA(fp16) = gelu(hA1 @ W1^T + b1)   K=512
        gemm_mma<2><<<dim3(DFF/256, MM/128), 256, GSMEM>>>(
            hA1, DD, W1T + (size_t)l*DFF*DD, DD, DD,
            nullptr, hidA, DFF, b1 + l * DFF, nullptr);

        // x = x + hid @ W2 + b2   K=2048
        gemm_mma<1><<<dim3(DD/256, MM/128), 256, GSMEM>>>(
            hidA, DFF, W2T + (size_t)l*DD*DFF, DFF, DFF,
            x, nullptr, DD, b2 + l * DD, x);
    }

    ln_kernel<<<MM, 128>>>(x, lnfg, lnfb, h);
    unembed_kernel<<<MM / UROWS, 128>>>(h, Wu, bu, logits_dst);
    loss_kernel<<<MM / 4, 128>>>(logits_dst, tgt);

    if (logits_dst != out) {
        int ncopy = out_size < nlog ? out_size : nlog;
        if (ncopy > 0)
            copy_out_kernel<<<(ncopy + 255) / 256, 256>>>(lg, out, ncopy);
    }
    if (out_size > nlog) {
        int tail = out_size - nlog;
        write_loss_kernel<<<(tail + 127) / 128, 128>>>(out, nlog, out_size);
    }
}

// round 9
// speedup vs baseline: 3.1378x; 1.0692x over previous
#include <cuda_runtime.h>
#include <cuda_fp16.h>
#include <math.h>
#include <stdint.h>

// Problem constants
#define LL   8
#define DD   512
#define HH   8
#define DHH  64
#define SS   64
#define VV   66
#define BB   256
#define MM   (BB * SS)      // 16384 token rows
#define DFF  (4 * DD)       // 2048
#define KQKV (3 * DD)       // 1536

// ---------------- scratch (static device allocations; no cudaMalloc) -------
__device__ float g_x[(size_t)MM * DD];
__device__ float g_h[(size_t)MM * DD];
__device__ __half g_qkv[(size_t)MM * KQKV];      // fp16 qkv [M, 1536]
__device__ __half g_hA1[(size_t)MM * DD];        // single-fp16 LN out
__device__ __half g_oA[(size_t)MM * DD];         // single-fp16 attn out
__device__ __half g_hidA[(size_t)MM * DFF];      // single-fp16 gelu out
__device__ float g_logits[(size_t)MM * VV];
__device__ float g_loss;

// fp16 transposed weights (all single)
__device__ __half g_Wqkv[(size_t)LL * KQKV * DD];   // [1536][512]
__device__ __half g_WoT [(size_t)LL * DD * DD];     // [512][512]
__device__ __half g_W1T [(size_t)LL * DFF * DD];    // [2048][512]
__device__ __half g_W2T [(size_t)LL * DD * DFF];    // [512][2048]

// ============================ PTX helpers ===================================
__device__ __forceinline__ uint32_t smem_u32(const void* p) {
    uint32_t a;
    asm("{ .reg .u64 t; cvta.to.shared.u64 t, %1; cvt.u32.u64 %0, t; }"
        : "=r"(a) : "l"(p));
    return a;
}
__device__ __forceinline__ void cp16(uint32_t s, const void* g) {
    asm volatile("cp.async.cg.shared.global [%0], [%1], 16;" :: "r"(s), "l"(g));
}
__device__ __forceinline__ void cp_commit() {
    asm volatile("cp.async.commit_group;" ::: "memory");
}
template<int N>
__device__ __forceinline__ void cp_wait() {
    asm volatile("cp.async.wait_group %0;" :: "n"(N) : "memory");
}
__device__ __forceinline__ void ldsm4(uint32_t* r, uint32_t addr) {
    asm volatile("ldmatrix.sync.aligned.m8n8.x4.shared.b16 {%0,%1,%2,%3}, [%4];"
        : "=r"(r[0]), "=r"(r[1]), "=r"(r[2]), "=r"(r[3]) : "r"(addr));
}
__device__ __forceinline__ void ldsm4t(uint32_t* r, uint32_t addr) {
    asm volatile("ldmatrix.sync.aligned.m8n8.x4.trans.shared.b16 {%0,%1,%2,%3}, [%4];"
        : "=r"(r[0]), "=r"(r[1]), "=r"(r[2]), "=r"(r[3]) : "r"(addr));
}
__device__ __forceinline__ void mma16816(float* d, const uint32_t* a, uint32_t b0, uint32_t b1) {
    asm volatile(
        "mma.sync.aligned.m16n8k16.row.col.f32.f16.f16.f32 "
        "{%0,%1,%2,%3}, {%4,%5,%6,%7}, {%8,%9}, {%0,%1,%2,%3};"
        : "+f"(d[0]), "+f"(d[1]), "+f"(d[2]), "+f"(d[3])
        : "r"(a[0]), "r"(a[1]), "r"(a[2]), "r"(a[3]), "r"(b0), "r"(b1));
}
__device__ __forceinline__ uint32_t pack_h2(float x, float y) {
    __half2 h = __halves2half2(__float2half_rn(x), __float2half_rn(y));
    return *(uint32_t*)&h;
}

// ============================ HMMA GEMM =====================================
// C[M,N] = A[M,K3] @ B[N,K3]^T, fp16 K-major.
// CTA tile 128x128, 128 threads (4 warps of 64x64), BK=64, 3-stage cp.async,
// 2 CTAs/SM co-resident (wave-quantization smoothing + cross-CTA overlap).
// EPI 0: C2 fp16 = acc
// EPI 1: C fp32 = acc + bias + res  (res==C aliasing ok)
// EPI 2: C2 fp16 = gelu(acc + bias)
#define STG       3
#define STG_BYTES 32768u   // A 16KB + B 16KB per stage
#define GSMEM     (STG * 32768)

template<int EPI>
__global__ void __launch_bounds__(128, 2)
gemm_mma(const __half* __restrict__ A, int lda,
         const __half* __restrict__ B, int ldb,
         int K3,
         float* __restrict__ C, __half* __restrict__ C2, int ldc,
         const float* __restrict__ bias,
         float* __restrict__ res)
{
    extern __shared__ char smem[];
    const int t    = threadIdx.x;
    const int wid  = t >> 5, lane = t & 31;
    const int brow = blockIdx.y * 128;
    const int bcol = blockIdx.x * 128;
    const int wm   = (wid & 1) * 64;
    const int wn   = (wid >> 1) * 64;

    uint32_t sbase = smem_u32(smem);

    float acc[4][8][4];
    #pragma unroll
    for (int i = 0; i < 4; i++)
        #pragma unroll
        for (int j = 0; j < 8; j++)
            #pragma unroll
            for (int e = 0; e < 4; e++) acc[i][j][e] = 0.0f;

    auto load_stage = [&](int s) {
        int buf = s % STG;
        int k0  = s << 6;
        uint32_t sa = sbase + buf * STG_BYTES;
        uint32_t sb = sa + 16384u;
        #pragma unroll
        for (int i = 0; i < 8; i++) {          // A: 1024 cp16
            int c   = t + (i << 7);
            int row = c >> 3;
            int c16 = c & 7;
            uint32_t off = (uint32_t)(row * 128 + c16 * 16);
            off ^= (off >> 3) & 0x70u;
            cp16(sa + off, A + (size_t)(brow + row) * lda + k0 + c16 * 8);
        }
        #pragma unroll
        for (int i = 0; i < 8; i++) {          // B: 1024 cp16
            int c   = t + (i << 7);
            int row = c >> 3;
            int c16 = c & 7;
            uint32_t off = (uint32_t)(row * 128 + c16 * 16);
            off ^= (off >> 3) & 0x70u;
            cp16(sb + off, B + (size_t)(bcol + row) * ldb + k0 + c16 * 8);
        }
        cp_commit();
    };

    const int S = K3 >> 6;

    const int lrow = ((lane >> 3) & 1) * 8 + (lane & 7);
    const int lkb  = (lane >> 4) * 16;

    load_stage(0);
    load_stage(1);

    for (int s = 0; s < S; s++) {
        int buf = s % STG;
        cp_wait<1>();
        __syncthreads();

        uint32_t sa = sbase + buf * STG_BYTES;
        uint32_t sb = sa + 16384u;

        #pragma unroll
        for (int kk = 0; kk < 4; kk++) {
            int kbyte = kk * 32 + lkb;

            uint32_t afr[4][4];
            #pragma unroll
            for (int mi = 0; mi < 4; mi++) {
                uint32_t off = (uint32_t)((wm + mi * 16 + lrow) * 128 + kbyte);
                off ^= (off >> 3) & 0x70u;
                ldsm4(afr[mi], sa + off);
            }
            uint32_t bfr[4][4];
            #pragma unroll
            for (int nj = 0; nj < 4; nj++) {
                uint32_t off = (uint32_t)((wn + nj * 16 + lrow) * 128 + kbyte);
                off ^= (off >> 3) & 0x70u;
                ldsm4(bfr[nj], sb + off);
            }
            #pragma unroll
            for (int mi = 0; mi < 4; mi++) {
                #pragma unroll
                for (int nj = 0; nj < 4; nj++) {
                    mma16816(acc[mi][2 * nj],     afr[mi], bfr[nj][0], bfr[nj][2]);
                    mma16816(acc[mi][2 * nj + 1], afr[mi], bfr[nj][1], bfr[nj][3]);
                }
            }
        }
        __syncthreads();
        if (s + 2 < S) load_stage(s + 2);
    }

    #pragma unroll
    for (int mi = 0; mi < 4; mi++) {
        #pragma unroll
        for (int ni = 0; ni < 8; ni++) {
            int r0 = brow + wm + mi * 16 + (lane >> 2);
            int c0 = bcol + wn + ni * 8 + ((lane & 3) << 1);
            #pragma unroll
            for (int half = 0; half < 2; half++) {
                int row = r0 + half * 8;
                float v0 = acc[mi][ni][half * 2];
                float v1 = acc[mi][ni][half * 2 + 1];
                if (EPI == 0) {
                    *(uint32_t*)&C2[(size_t)row * ldc + c0] = pack_h2(v0, v1);
                } else if (EPI == 1) {
                    float2 bv = *(const float2*)&bias[c0];
                    float2 r  = *(const float2*)&res[(size_t)row * ldc + c0];
                    *(float2*)&C[(size_t)row * ldc + c0] =
                        make_float2(v0 + bv.x + r.x, v1 + bv.y + r.y);
                } else {
                    float2 bv = *(const float2*)&bias[c0];
                    float a0 = v0 + bv.x;
                    float a1 = v1 + bv.y;
                    float g0 = 0.5f * a0 * (1.0f + erff(a0 * 0.70710678118654752f));
                    float g1 = 0.5f * a1 * (1.0f + erff(a1 * 0.70710678118654752f));
                    *(uint32_t*)&C2[(size_t)row * ldc + c0] = pack_h2(g0, g1);
                }
            }
        }
    }
}

// ============================ weight prep ===================================
__global__ void __launch_bounds__(256) prep_w_single(
    const float* __restrict__ W, int K, int N,
    __half* __restrict__ out, size_t outLayer)
{
    __shared__ float ts[32][33];
    int l  = blockIdx.z;
    const float* Wl = W + (size_t)l * K * N;
    __half* ol = out + (size_t)l * outLayer;
    int k0 = blockIdx.x * 32, n0 = blockIdx.y * 32;
    int tx = threadIdx.x, ty = threadIdx.y;   // 32 x 8
    #pragma unroll
    for (int i = 0; i < 32; i += 8)
        ts[ty + i][tx] = Wl[(size_t)(k0 + ty + i) * N + n0 + tx];
    __syncthreads();
    #pragma unroll
    for (int i = 0; i < 32; i += 8) {
        int n = n0 + ty + i, k = k0 + tx;
        ol[(size_t)n * K + k] = __float2half_rn(ts[tx][ty + i]);
    }
}

// ---------------- embedding + loss reset ------------------------------------
__global__ void __launch_bounds__(256) embed_kernel(
    const int* __restrict__ ids, const float* __restrict__ tok,
    const float* __restrict__ pos, float* __restrict__ x)
{
    int i = blockIdx.x * 256 + threadIdx.x;
    if (i == 0) g_loss = 0.0f;
    if (i >= MM * DD) return;
    int row = i / DD;
    int d   = i - row * DD;
    int s   = row % SS;
    x[i] = tok[(size_t)ids[row] * DD + d] + pos[(size_t)s * DD + d];
}

// ---------------- LayerNorm core (unbiased std, eps on std) -----------------
__device__ __forceinline__ void ln_stats(const float4& v, int t, float& mean, float& inv)
{
    float s  = v.x + v.y + v.z + v.w;
    float ss = v.x * v.x + v.y * v.y + v.z * v.z + v.w * v.w;
    #pragma unroll
    for (int o = 16; o; o >>= 1) {
        s  += __shfl_xor_sync(0xffffffffu, s,  o);
        ss += __shfl_xor_sync(0xffffffffu, ss, o);
    }
    __shared__ float sh[8];
    int wid = t >> 5, lane = t & 31;
    if (lane == 0) { sh[wid * 2] = s; sh[wid * 2 + 1] = ss; }
    __syncthreads();
    s  = sh[0] + sh[2] + sh[4] + sh[6];
    ss = sh[1] + sh[3] + sh[5] + sh[7];
    mean = s * (1.0f / DD);
    float var = (ss - s * mean) * (1.0f / (DD - 1));
    inv = 1.0f / (sqrtf(fmaxf(var, 0.0f)) + 1e-10f);
}

__global__ void __launch_bounds__(128) ln_kernel(
    const float* __restrict__ x, const float* __restrict__ g,
    const float* __restrict__ b, float* __restrict__ out)
{
    int row = blockIdx.x, t = threadIdx.x;
    float4 v = ((const float4*)(x + (size_t)row * DD))[t];
    float mean, inv;
    ln_stats(v, t, mean, inv);
    float4 gv = ((const float4*)g)[t], bv = ((const float4*)b)[t];
    float4 ov;
    ov.x = (v.x - mean) * inv * gv.x + bv.x;
    ov.y = (v.y - mean) * inv * gv.y + bv.y;
    ov.z = (v.z - mean) * inv * gv.z + bv.z;
    ov.w = (v.w - mean) * inv * gv.w + bv.w;
    ((float4*)(out + (size_t)row * DD))[t] = ov;
}

// LN -> single fp16 [M,512]
__global__ void __launch_bounds__(128) ln_single_kernel(
    const float* __restrict__ x, const float* __restrict__ g,
    const float* __restrict__ b, __half* __restrict__ out)
{
    int row = blockIdx.x, t = threadIdx.x;
    float4 v = ((const float4*)(x + (size_t)row * DD))[t];
    float mean, inv;
    ln_stats(v, t, mean, inv);
    float4 gv = ((const float4*)g)[t], bv = ((const float4*)b)[t];
    size_t ro = (size_t)row * DD + t * 4;
    *(uint32_t*)&out[ro]     = pack_h2((v.x - mean) * inv * gv.x + bv.x,
                                       (v.y - mean) * inv * gv.y + bv.y);
    *(uint32_t*)&out[ro + 2] = pack_h2((v.z - mean) * inv * gv.z + bv.z,
                                       (v.w - mean) * inv * gv.w + bv.w);
}

// ---------------- MMA causal attention per (b,h) -----------------------------
__global__ void __launch_bounds__(128) attn_mma_kernel(
    const __half* __restrict__ qkv, __half* __restrict__ oA)
{
    __shared__ __align__(16) char smem[3 * 8192];  // q,k,v tiles 64x128B SW128

    int bh = blockIdx.x;
    int b  = bh >> 3;
    int h  = bh & 7;
    const __half* qb = qkv + (size_t)b * SS * KQKV + h * DHH;
    const __half* kb = qb + DD;
    const __half* vb = qb + 2 * DD;
    __half* ob = oA + (size_t)b * SS * DD + h * DHH;

    uint32_t sq = smem_u32(smem);
    uint32_t sk = sq + 8192u;
    uint32_t sv = sq + 16384u;

    int t = threadIdx.x, wid = t >> 5, lane = t & 31;

    for (int i = t; i < 512; i += 128) {
        int row = i >> 3, c = i & 7;
        uint32_t off = (uint32_t)(row * 128 + c * 16);
        off ^= (off >> 3) & 0x70u;
        const size_t go = (size_t)row * KQKV + c * 8;
        cp16(sq + off, qb + go);
        cp16(sk + off, kb + go);
        cp16(sv + off, vb + go);
    }
    cp_commit();
    cp_wait<0>();
    __syncthreads();

    const int m0   = wid * 16;
    const int lrow = ((lane >> 3) & 1) * 8 + (lane & 7);
    const int lkb  = (lane >> 4) * 16;

    float sc[8][4];
    #pragma unroll
    for (int i = 0; i < 8; i++)
        #pragma unroll
        for (int e = 0; e < 4; e++) sc[i][e] = 0.0f;

    #pragma unroll
    for (int kk = 0; kk < 4; kk++) {
        int kbyte = kk * 32 + lkb;
        uint32_t aoff = (uint32_t)((m0 + lrow) * 128 + kbyte);
        aoff ^= (aoff >> 3) & 0x70u;
        uint32_t afr[4];
        ldsm4(afr, sq + aoff);
        #pragma unroll
        for (int nj = 0; nj < 4; nj++) {
            uint32_t boff = (uint32_t)((nj * 16 + lrow) * 128 + kbyte);
            boff ^= (boff >> 3) & 0x70u;
            uint32_t bfr[4];
            ldsm4(bfr, sk + boff);
            mma16816(sc[2 * nj],     afr, bfr[0], bfr[2]);
            mma16816(sc[2 * nj + 1], afr, bfr[1], bfr[3]);
        }
    }

    const float scale = 0.044194173824159216f;  // 1/sqrt(512)
    int r_lo = m0 + (lane >> 2);
    int r_hi = r_lo + 8;
    float mx0 = -1e30f, mx1 = -1e30f;
    #pragma unroll
    for (int nt = 0; nt < 8; nt++) {
        int c0 = nt * 8 + ((lane & 3) << 1);
        sc[nt][0] = (c0     <= r_lo) ? sc[nt][0] * scale : -1e30f;
        sc[nt][1] = (c0 + 1 <= r_lo) ? sc[nt][1] * scale : -1e30f;
        sc[nt][2] = (c0     <= r_hi) ? sc[nt][2] * scale : -1e30f;
        sc[nt][3] = (c0 + 1 <= r_hi) ? sc[nt][3] * scale : -1e30f;
        mx0 = fmaxf(mx0, fmaxf(sc[nt][0], sc[nt][1]));
        mx1 = fmaxf(mx1, fmaxf(sc[nt][2], sc[nt][3]));
    }
    mx0 = fmaxf(mx0, __shfl_xor_sync(0xffffffffu, mx0, 1));
    mx0 = fmaxf(mx0, __shfl_xor_sync(0xffffffffu, mx0, 2));
    mx1 = fmaxf(mx1, __shfl_xor_sync(0xffffffffu, mx1, 1));
    mx1 = fmaxf(mx1, __shfl_xor_sync(0xffffffffu, mx1, 2));

    float sum0 = 0.0f, sum1 = 0.0f;
    #pragma unroll
    for (int nt = 0; nt < 8; nt++) {
        sc[nt][0] = __expf(sc[nt][0] - mx0);
        sc[nt][1] = __expf(sc[nt][1] - mx0);
        sc[nt][2] = __expf(sc[nt][2] - mx1);
        sc[nt][3] = __expf(sc[nt][3] - mx1);
        sum0 += sc[nt][0] + sc[nt][1];
        sum1 += sc[nt][2] + sc[nt][3];
    }
    sum0 += __shfl_xor_sync(0xffffffffu, sum0, 1);
    sum0 += __shfl_xor_sync(0xffffffffu, sum0, 2);
    sum1 += __shfl_xor_sync(0xffffffffu, sum1, 1);
    sum1 += __shfl_xor_sync(0xffffffffu, sum1, 2);
    float inv0 = 1.0f / sum0, inv1 = 1.0f / sum1;

    float oacc[8][4];
    #pragma unroll
    for (int i = 0; i < 8; i++)
        #pragma unroll
        for (int e = 0; e < 4; e++) oacc[i][e] = 0.0f;

    int jrow = lane & 15;
    int echunk = (lane >> 4) * 16;
    #pragma unroll
    for (int kk = 0; kk < 4; kk++) {
        uint32_t afr[4];
        afr[0] = pack_h2(sc[2 * kk][0] * inv0,     sc[2 * kk][1] * inv0);
        afr[1] = pack_h2(sc[2 * kk][2] * inv1,     sc[2 * kk][3] * inv1);
        afr[2] = pack_h2(sc[2 * kk + 1][0] * inv0, sc[2 * kk + 1][1] * inv0);
        afr[3] = pack_h2(sc[2 * kk + 1][2] * inv1, sc[2 * kk + 1][3] * inv1);

        #pragma unroll
        for (int ne = 0; ne < 4; ne++) {
            uint32_t boff = (uint32_t)((kk * 16 + jrow) * 128 + ne * 32 + echunk);
            boff ^= (boff >> 3) & 0x70u;
            uint32_t bfr[4];
            ldsm4t(bfr, sv + boff);
            mma16816(oacc[2 * ne],     afr, bfr[0], bfr[1]);
            mma16816(oacc[2 * ne + 1], afr, bfr[2], bfr[3]);
        }
    }

    #pragma unroll
    for (int nt = 0; nt < 8; nt++) {
        int e = nt * 8 + ((lane & 3) << 1);
        *(uint32_t*)&ob[(size_t)r_lo * DD + e] = pack_h2(oacc[nt][0], oacc[nt][1]);
        *(uint32_t*)&ob[(size_t)r_hi * DD + e] = pack_h2(oacc[nt][2], oacc[nt][3]);
    }
}

// ---------------- fused unembed + cross-entropy loss ------------------------
#define UROWS 16
__global__ void __launch_bounds__(128) unembed_loss_kernel(
    const float* __restrict__ x, const float* __restrict__ Wu,
    const float* __restrict__ bu, const int* __restrict__ tgt,
    float* __restrict__ logits)
{
    __shared__ float xs[UROWS][DD];
    __shared__ float lgs[UROWS][VV + 2];
    int r0 = blockIdx.x * UROWS;
    const float4* src = (const float4*)(x + (size_t)r0 * DD);
    float4* dst = (float4*)&xs[0][0];
    for (int i = threadIdx.x; i < UROWS * DD / 4; i += 128)
        dst[i] = src[i];
    __syncthreads();
    int c = threadIdx.x;
    if (c < VV) {
        float acc[UROWS];
        float bc = bu[c];
        #pragma unroll
        for (int r = 0; r < UROWS; r++) acc[r] = bc;
        #pragma unroll 4
        for (int k = 0; k < DD; k++) {
            float w = Wu[(size_t)k * VV + c];
            #pragma unroll
            for (int r = 0; r < UROWS; r++)
                acc[r] = fmaf(xs[r][k], w, acc[r]);
        }
        #pragma unroll
        for (int r = 0; r < UROWS; r++) {
            logits[(size_t)(r0 + r) * VV + c] = acc[r];
            lgs[r][c] = acc[r];
        }
    }
    __syncthreads();

    // loss: warp w handles rows 4w .. 4w+3
    int wid = threadIdx.x >> 5, lane = threadIdx.x & 31;
    float part = 0.0f;
    #pragma unroll
    for (int rr = 0; rr < 4; rr++) {
        int r = wid * 4 + rr;
        float l0 = lgs[r][lane];
        float l1 = lgs[r][lane + 32];
        float l2 = (lane + 64 < VV) ? lgs[r][lane + 64] : -1e30f;
        float m = fmaxf(fmaxf(l0, l1), l2);
        #pragma unroll
        for (int off = 16; off; off >>= 1)
            m = fmaxf(m, __shfl_xor_sync(0xffffffffu, m, off));
        float sum = expf(l0 - m) + expf(l1 - m) +
                    ((lane + 64 < VV) ? expf(l2 - m) : 0.0f);
        #pragma unroll
        for (int off = 16; off; off >>= 1)
            sum += __shfl_xor_sync(0xffffffffu, sum, off);
        if (lane == 0)
            part += (m + logf(sum)) - lgs[r][tgt[r0 + r]];
    }
    if (lane == 0) atomicAdd(&g_loss, part);
}

// ---------------- output assembly -------------------------------------------
__global__ void __launch_bounds__(256) copy_out_kernel(
    const float* __restrict__ lg, float* __restrict__ out, int n)
{
    int i = blockIdx.x * 256 + threadIdx.x;
    if (i < n) out[i] = lg[i];
}
__global__ void __launch_bounds__(128) write_loss_kernel(
    float* __restrict__ out, int lo, int hi)
{
    int i = lo + blockIdx.x * 128 + threadIdx.x;
    if (i < hi) out[i] = g_loss * (1.0f / (float)MM);
}

// ---------------- launcher ----------------------------------------------------
extern "C" void kernel_launch(void* const* d_in, const int* in_sizes, int n_in,
                              void* d_out, int out_size)
{
    const int*   ids  = (const int*)d_in[0];
    const int*   tgt  = (const int*)d_in[1];
    const float* tok  = (const float*)d_in[2];
    const float* pos  = (const float*)d_in[3];
    const float* Wq   = (const float*)d_in[4];
    const float* Wk   = (const float*)d_in[5];
    const float* Wv   = (const float*)d_in[6];
    const float* Wo   = (const float*)d_in[7];
    const float* bo   = (const float*)d_in[8];
    const float* W1   = (const float*)d_in[9];
    const float* b1   = (const float*)d_in[10];
    const float* W2   = (const float*)d_in[11];
    const float* b2   = (const float*)d_in[12];
    const float* ln1g = (const float*)d_in[13];
    const float* ln1b = (const float*)d_in[14];
    const float* ln2g = (const float*)d_in[15];
    const float* ln2b = (const float*)d_in[16];
    const float* lnfg = (const float*)d_in[17];
    const float* lnfb = (const float*)d_in[18];
    const float* Wu   = (const float*)d_in[19];
    const float* bu   = (const float*)d_in[20];
    float* out = (float*)d_out;

    float *x, *h, *lg;
    __half *qkv, *hA1, *oA, *hidA, *Wqkv, *WoT, *W1T, *W2T;
    cudaGetSymbolAddress((void**)&x,    g_x);
    cudaGetSymbolAddress((void**)&h,    g_h);
    cudaGetSymbolAddress((void**)&qkv,  g_qkv);
    cudaGetSymbolAddress((void**)&hA1,  g_hA1);
    cudaGetSymbolAddress((void**)&oA,   g_oA);
    cudaGetSymbolAddress((void**)&hidA, g_hidA);
    cudaGetSymbolAddress((void**)&lg,   g_logits);
    cudaGetSymbolAddress((void**)&Wqkv, g_Wqkv);
    cudaGetSymbolAddress((void**)&WoT,  g_WoT);
    cudaGetSymbolAddress((void**)&W1T,  g_W1T);
    cudaGetSymbolAddress((void**)&W2T,  g_W2T);

    cudaFuncSetAttribute(gemm_mma<0>, cudaFuncAttributeMaxDynamicSharedMemorySize, GSMEM);
    cudaFuncSetAttribute(gemm_mma<1>, cudaFuncAttributeMaxDynamicSharedMemorySize, GSMEM);
    cudaFuncSetAttribute(gemm_mma<2>, cudaFuncAttributeMaxDynamicSharedMemorySize, GSMEM);

    int nlog = MM * VV;
    float* logits_dst = (out_size >= nlog) ? out : lg;

    // ---- weight prep: 6 launches (grid.z = layer) ----
    dim3 pb(32, 8);
    prep_w_single<<<dim3(DD/32, DD/32, LL), pb>>>(Wq, DD, DD,
        Wqkv,                       (size_t)KQKV * DD);
    prep_w_single<<<dim3(DD/32, DD/32, LL), pb>>>(Wk, DD, DD,
        Wqkv + (size_t)DD * DD,     (size_t)KQKV * DD);
    prep_w_single<<<dim3(DD/32, DD/32, LL), pb>>>(Wv, DD, DD,
        Wqkv + (size_t)2 * DD * DD, (size_t)KQKV * DD);
    prep_w_single<<<dim3(DD/32, DD/32, LL), pb>>>(Wo, DD, DD,
        WoT,  (size_t)DD * DD);
    prep_w_single<<<dim3(DD/32, DFF/32, LL), pb>>>(W1, DD, DFF,
        W1T,  (size_t)DFF * DD);
    prep_w_single<<<dim3(DFF/32, DD/32, LL), pb>>>(W2, DFF, DD,
        W2T,  (size_t)DD * DFF);

    embed_kernel<<<(MM * DD + 255) / 256, 256>>>(ids, tok, pos, x);

    for (int l = 0; l < LL; l++) {
        ln_single_kernel<<<MM, 128>>>(x, ln1g + l * DD, ln1b + l * DD, hA1);

        // qkv(fp16) = hA1 @ Wqkv^T   K=512
        gemm_mma<0><<<dim3(KQKV/128, MM/128), 128, GSMEM>>>(
            hA1, DD, Wqkv + (size_t)l*KQKV*DD, DD, DD,
            nullptr, qkv, KQKV, nullptr, nullptr);

        attn_mma_kernel<<<BB * HH, 128>>>(qkv, oA);

        // x = x + o @ Wo + bo    K=512
        gemm_mma<1><<<dim3(DD/128, MM/128), 128, GSMEM>>>(
            oA, DD, WoT + (size_t)l*DD*DD, DD, DD,
            x, nullptr, DD, bo + l * DD, x);

        ln_single_kernel<<<MM, 128>>>(x, ln2g + l * DD, ln2b + l * DD, hA1);

        // hidA(fp16) = gelu(hA1 @ W1^T + b1)   K=512
        gemm_mma<2><<<dim3(DFF/128, MM/128), 128, GSMEM>>>(
            hA1, DD, W1T + (size_t)l*DFF*DD, DD, DD,
            nullptr, hidA, DFF, b1 + l * DFF, nullptr);

        // x = x + hid @ W2 + b2   K=2048
        gemm_mma<1><<<dim3(DD/128, MM/128), 128, GSMEM>>>(
            hidA, DFF, W2T + (size_t)l*DD*DFF, DFF, DFF,
            x, nullptr, DD, b2 + l * DD, x);
    }

    ln_kernel<<<MM, 128>>>(x, lnfg, lnfb, h);
    unembed_loss_kernel<<<MM / UROWS, 128>>>(h, Wu, bu, tgt, logits_dst);

    if (logits_dst != out) {
        int ncopy = out_size < nlog ? out_size : nlog;
        if (ncopy > 0)
            copy_out_kernel<<<(ncopy + 255) / 256, 256>>>(lg, out, ncopy);
    }
    if (out_size > nlog) {
        int tail = out_size - nlog;
        write_loss_kernel<<<(tail + 127) / 128, 128>>>(out, nlog, out_size);
    }
}

// round 10
// speedup vs baseline: 3.2040x; 1.0211x over previous
#include <cuda_runtime.h>
#include <cuda_fp16.h>
#include <math.h>
#include <stdint.h>

// Problem constants
#define LL   8
#define DD   512
#define HH   8
#define DHH  64
#define SS   64
#define VV   66
#define BB   256
#define MM   (BB * SS)      // 16384 token rows
#define DFF  (4 * DD)       // 2048
#define KQKV (3 * DD)       // 1536

// ---------------- scratch (static device allocations; no cudaMalloc) -------
__device__ float g_x[(size_t)MM * DD];
__device__ float g_h[(size_t)MM * DD];
__device__ __half g_qkv[(size_t)MM * KQKV];      // fp16 qkv [M, 1536]
__device__ __half g_hA1[(size_t)MM * DD];        // single-fp16 LN out
__device__ __half g_oA[(size_t)MM * DD];         // single-fp16 attn out
__device__ __half g_hidA[(size_t)MM * DFF];      // single-fp16 gelu out
__device__ float g_logits[(size_t)MM * VV];
__device__ float g_loss;

// fp16 transposed weights (all single)
__device__ __half g_Wqkv[(size_t)LL * KQKV * DD];   // [1536][512]
__device__ __half g_WoT [(size_t)LL * DD * DD];     // [512][512]
__device__ __half g_W1T [(size_t)LL * DFF * DD];    // [2048][512]
__device__ __half g_W2T [(size_t)LL * DD * DFF];    // [512][2048]

// ============================ PTX helpers ===================================
__device__ __forceinline__ uint32_t smem_u32(const void* p) {
    uint32_t a;
    asm("{ .reg .u64 t; cvta.to.shared.u64 t, %1; cvt.u32.u64 %0, t; }"
        : "=r"(a) : "l"(p));
    return a;
}
__device__ __forceinline__ void cp16(uint32_t s, const void* g) {
    asm volatile("cp.async.cg.shared.global [%0], [%1], 16;" :: "r"(s), "l"(g));
}
__device__ __forceinline__ void cp_commit() {
    asm volatile("cp.async.commit_group;" ::: "memory");
}
template<int N>
__device__ __forceinline__ void cp_wait() {
    asm volatile("cp.async.wait_group %0;" :: "n"(N) : "memory");
}
__device__ __forceinline__ void ldsm4(uint32_t* r, uint32_t addr) {
    asm volatile("ldmatrix.sync.aligned.m8n8.x4.shared.b16 {%0,%1,%2,%3}, [%4];"
        : "=r"(r[0]), "=r"(r[1]), "=r"(r[2]), "=r"(r[3]) : "r"(addr));
}
__device__ __forceinline__ void ldsm4t(uint32_t* r, uint32_t addr) {
    asm volatile("ldmatrix.sync.aligned.m8n8.x4.trans.shared.b16 {%0,%1,%2,%3}, [%4];"
        : "=r"(r[0]), "=r"(r[1]), "=r"(r[2]), "=r"(r[3]) : "r"(addr));
}
__device__ __forceinline__ void mma16816(float* d, const uint32_t* a, uint32_t b0, uint32_t b1) {
    asm volatile(
        "mma.sync.aligned.m16n8k16.row.col.f32.f16.f16.f32 "
        "{%0,%1,%2,%3}, {%4,%5,%6,%7}, {%8,%9}, {%0,%1,%2,%3};"
        : "+f"(d[0]), "+f"(d[1]), "+f"(d[2]), "+f"(d[3])
        : "r"(a[0]), "r"(a[1]), "r"(a[2]), "r"(a[3]), "r"(b0), "r"(b1));
}
__device__ __forceinline__ uint32_t pack_h2(float x, float y) {
    __half2 h = __halves2half2(__float2half_rn(x), __float2half_rn(y));
    return *(uint32_t*)&h;
}

// ============================ HMMA GEMM =====================================
// C[M,N] = A[M,K3] @ B[N,K3]^T, fp16 K-major.
// CTA tile 128x128, 128 threads (4 warps of 64x64), BK=64, 3-stage cp.async,
// 2 CTAs/SM co-resident.
// EPI 0: C2 fp16 = acc
// EPI 1: C fp32 = acc + bias + res  (res==C aliasing ok)
// EPI 2: C2 fp16 = gelu(acc + bias)
#define STG       3
#define STG_BYTES 32768u   // A 16KB + B 16KB per stage
#define GSMEM     (STG * 32768)

template<int EPI>
__global__ void __launch_bounds__(128, 2)
gemm_mma(const __half* __restrict__ A, int lda,
         const __half* __restrict__ B, int ldb,
         int K3,
         float* __restrict__ C, __half* __restrict__ C2, int ldc,
         const float* __restrict__ bias,
         float* __restrict__ res)
{
    extern __shared__ char smem[];
    const int t    = threadIdx.x;
    const int wid  = t >> 5, lane = t & 31;
    const int brow = blockIdx.y * 128;
    const int bcol = blockIdx.x * 128;
    const int wm   = (wid & 1) * 64;
    const int wn   = (wid >> 1) * 64;

    uint32_t sbase = smem_u32(smem);

    float acc[4][8][4];
    #pragma unroll
    for (int i = 0; i < 4; i++)
        #pragma unroll
        for (int j = 0; j < 8; j++)
            #pragma unroll
            for (int e = 0; e < 4; e++) acc[i][j][e] = 0.0f;

    auto load_stage = [&](int s) {
        int buf = s % STG;
        int k0  = s << 6;
        uint32_t sa = sbase + buf * STG_BYTES;
        uint32_t sb = sa + 16384u;
        #pragma unroll
        for (int i = 0; i < 8; i++) {          // A: 1024 cp16
            int c   = t + (i << 7);
            int row = c >> 3;
            int c16 = c & 7;
            uint32_t off = (uint32_t)(row * 128 + c16 * 16);
            off ^= (off >> 3) & 0x70u;
            cp16(sa + off, A + (size_t)(brow + row) * lda + k0 + c16 * 8);
        }
        #pragma unroll
        for (int i = 0; i < 8; i++) {          // B: 1024 cp16
            int c   = t + (i << 7);
            int row = c >> 3;
            int c16 = c & 7;
            uint32_t off = (uint32_t)(row * 128 + c16 * 16);
            off ^= (off >> 3) & 0x70u;
            cp16(sb + off, B + (size_t)(bcol + row) * ldb + k0 + c16 * 8);
        }
        cp_commit();
    };

    const int S = K3 >> 6;

    const int lrow = ((lane >> 3) & 1) * 8 + (lane & 7);
    const int lkb  = (lane >> 4) * 16;

    load_stage(0);
    load_stage(1);

    for (int s = 0; s < S; s++) {
        int buf = s % STG;
        cp_wait<1>();
        __syncthreads();

        uint32_t sa = sbase + buf * STG_BYTES;
        uint32_t sb = sa + 16384u;

        #pragma unroll
        for (int kk = 0; kk < 4; kk++) {
            int kbyte = kk * 32 + lkb;

            uint32_t afr[4][4];
            #pragma unroll
            for (int mi = 0; mi < 4; mi++) {
                uint32_t off = (uint32_t)((wm + mi * 16 + lrow) * 128 + kbyte);
                off ^= (off >> 3) & 0x70u;
                ldsm4(afr[mi], sa + off);
            }
            uint32_t bfr[4][4];
            #pragma unroll
            for (int nj = 0; nj < 4; nj++) {
                uint32_t off = (uint32_t)((wn + nj * 16 + lrow) * 128 + kbyte);
                off ^= (off >> 3) & 0x70u;
                ldsm4(bfr[nj], sb + off);
            }
            #pragma unroll
            for (int mi = 0; mi < 4; mi++) {
                #pragma unroll
                for (int nj = 0; nj < 4; nj++) {
                    mma16816(acc[mi][2 * nj],     afr[mi], bfr[nj][0], bfr[nj][2]);
                    mma16816(acc[mi][2 * nj + 1], afr[mi], bfr[nj][1], bfr[nj][3]);
                }
            }
        }
        __syncthreads();
        if (s + 2 < S) load_stage(s + 2);
    }

    #pragma unroll
    for (int mi = 0; mi < 4; mi++) {
        #pragma unroll
        for (int ni = 0; ni < 8; ni++) {
            int r0 = brow + wm + mi * 16 + (lane >> 2);
            int c0 = bcol + wn + ni * 8 + ((lane & 3) << 1);
            #pragma unroll
            for (int half = 0; half < 2; half++) {
                int row = r0 + half * 8;
                float v0 = acc[mi][ni][half * 2];
                float v1 = acc[mi][ni][half * 2 + 1];
                if (EPI == 0) {
                    *(uint32_t*)&C2[(size_t)row * ldc + c0] = pack_h2(v0, v1);
                } else if (EPI == 1) {
                    float2 bv = *(const float2*)&bias[c0];
                    float2 r  = *(const float2*)&res[(size_t)row * ldc + c0];
                    *(float2*)&C[(size_t)row * ldc + c0] =
                        make_float2(v0 + bv.x + r.x, v1 + bv.y + r.y);
                } else {
                    float2 bv = *(const float2*)&bias[c0];
                    float a0 = v0 + bv.x;
                    float a1 = v1 + bv.y;
                    float g0 = 0.5f * a0 * (1.0f + erff(a0 * 0.70710678118654752f));
                    float g1 = 0.5f * a1 * (1.0f + erff(a1 * 0.70710678118654752f));
                    *(uint32_t*)&C2[(size_t)row * ldc + c0] = pack_h2(g0, g1);
                }
            }
        }
    }
}

// ============================ weight prep ===================================
// Generic 32x32-tile transpose fp32->fp16 helper body.
__device__ __forceinline__ void prep_body(
    const float* __restrict__ Wl, int K, int N, __half* __restrict__ ol,
    int k0, int n0, int tx, int ty)
{
    __shared__ float ts[32][33];
    #pragma unroll
    for (int i = 0; i < 32; i += 8)
        ts[ty + i][tx] = Wl[(size_t)(k0 + ty + i) * N + n0 + tx];
    __syncthreads();
    #pragma unroll
    for (int i = 0; i < 32; i += 8) {
        int n = n0 + ty + i, k = k0 + tx;
        ol[(size_t)n * K + k] = __float2half_rn(ts[tx][ty + i]);
    }
}

// q/k/v/o weights, all [512,512]: grid.z = 4*layer + part
__global__ void __launch_bounds__(256) prep_w_qkvo(
    const float* __restrict__ Wq, const float* __restrict__ Wk,
    const float* __restrict__ Wv, const float* __restrict__ Wo,
    __half* __restrict__ Wqkv, __half* __restrict__ WoT)
{
    int z = blockIdx.z;
    int l = z >> 2, part = z & 3;
    const float* W = (part == 0) ? Wq : (part == 1) ? Wk : (part == 2) ? Wv : Wo;
    const float* Wl = W + (size_t)l * DD * DD;
    __half* ol = (part < 3)
        ? Wqkv + (size_t)l * KQKV * DD + (size_t)part * DD * DD
        : WoT  + (size_t)l * DD * DD;
    prep_body(Wl, DD, DD, ol, blockIdx.x * 32, blockIdx.y * 32,
              threadIdx.x, threadIdx.y);
}

__global__ void __launch_bounds__(256) prep_w_single(
    const float* __restrict__ W, int K, int N,
    __half* __restrict__ out, size_t outLayer)
{
    int l = blockIdx.z;
    prep_body(W + (size_t)l * K * N, K, N, out + (size_t)l * outLayer,
              blockIdx.x * 32, blockIdx.y * 32, threadIdx.x, threadIdx.y);
}

// ---------------- embedding + loss reset ------------------------------------
__global__ void __launch_bounds__(256) embed_kernel(
    const int* __restrict__ ids, const float* __restrict__ tok,
    const float* __restrict__ pos, float* __restrict__ x)
{
    int i = blockIdx.x * 256 + threadIdx.x;
    if (i == 0) g_loss = 0.0f;
    if (i >= MM * DD) return;
    int row = i / DD;
    int d   = i - row * DD;
    int s   = row % SS;
    x[i] = tok[(size_t)ids[row] * DD + d] + pos[(size_t)s * DD + d];
}

// ---------------- LayerNorm: warp-per-row (unbiased std, eps on std) --------
// 256 threads = 8 warps = 8 rows per block; lane holds 4 float4 (16 elems).
__device__ __forceinline__ void ln_warp_stats(const float4* v, float& mean, float& inv)
{
    float s = 0.0f, ss = 0.0f;
    #pragma unroll
    for (int j = 0; j < 4; j++) {
        s  += v[j].x + v[j].y + v[j].z + v[j].w;
        ss += v[j].x * v[j].x + v[j].y * v[j].y + v[j].z * v[j].z + v[j].w * v[j].w;
    }
    #pragma unroll
    for (int o = 16; o; o >>= 1) {
        s  += __shfl_xor_sync(0xffffffffu, s,  o);
        ss += __shfl_xor_sync(0xffffffffu, ss, o);
    }
    mean = s * (1.0f / DD);
    float var = (ss - s * mean) * (1.0f / (DD - 1));
    inv = 1.0f / (sqrtf(fmaxf(var, 0.0f)) + 1e-10f);
}

// fp32 output (final LN)
__global__ void __launch_bounds__(256) ln_kernel(
    const float* __restrict__ x, const float* __restrict__ g,
    const float* __restrict__ b, float* __restrict__ out)
{
    int warp = threadIdx.x >> 5, lane = threadIdx.x & 31;
    int row  = blockIdx.x * 8 + warp;
    const float4* xr = (const float4*)(x + (size_t)row * DD);
    const float4* gr = (const float4*)g;
    const float4* br = (const float4*)b;
    float4 v[4];
    #pragma unroll
    for (int j = 0; j < 4; j++) v[j] = xr[lane + 32 * j];
    float mean, inv;
    ln_warp_stats(v, mean, inv);
    float4* orow = (float4*)(out + (size_t)row * DD);
    #pragma unroll
    for (int j = 0; j < 4; j++) {
        float4 gv = gr[lane + 32 * j], bv = br[lane + 32 * j];
        float4 ov;
        ov.x = (v[j].x - mean) * inv * gv.x + bv.x;
        ov.y = (v[j].y - mean) * inv * gv.y + bv.y;
        ov.z = (v[j].z - mean) * inv * gv.z + bv.z;
        ov.w = (v[j].w - mean) * inv * gv.w + bv.w;
        orow[lane + 32 * j] = ov;
    }
}

// fp16 output (layer LNs)
__global__ void __launch_bounds__(256) ln_single_kernel(
    const float* __restrict__ x, const float* __restrict__ g,
    const float* __restrict__ b, __half* __restrict__ out)
{
    int warp = threadIdx.x >> 5, lane = threadIdx.x & 31;
    int row  = blockIdx.x * 8 + warp;
    const float4* xr = (const float4*)(x + (size_t)row * DD);
    const float4* gr = (const float4*)g;
    const float4* br = (const float4*)b;
    float4 v[4];
    #pragma unroll
    for (int j = 0; j < 4; j++) v[j] = xr[lane + 32 * j];
    float mean, inv;
    ln_warp_stats(v, mean, inv);
    uint2* orow = (uint2*)(out + (size_t)row * DD);
    #pragma unroll
    for (int j = 0; j < 4; j++) {
        float4 gv = gr[lane + 32 * j], bv = br[lane + 32 * j];
        uint2 o;
        o.x = pack_h2((v[j].x - mean) * inv * gv.x + bv.x,
                      (v[j].y - mean) * inv * gv.y + bv.y);
        o.y = pack_h2((v[j].z - mean) * inv * gv.z + bv.z,
                      (v[j].w - mean) * inv * gv.w + bv.w);
        orow[lane + 32 * j] = o;
    }
}

// ---------------- MMA causal attention per (b,h) -----------------------------
__global__ void __launch_bounds__(128) attn_mma_kernel(
    const __half* __restrict__ qkv, __half* __restrict__ oA)
{
    __shared__ __align__(16) char smem[3 * 8192];  // q,k,v tiles 64x128B SW128

    int bh = blockIdx.x;
    int b  = bh >> 3;
    int h  = bh & 7;
    const __half* qb = qkv + (size_t)b * SS * KQKV + h * DHH;
    const __half* kb = qb + DD;
    const __half* vb = qb + 2 * DD;
    __half* ob = oA + (size_t)b * SS * DD + h * DHH;

    uint32_t sq = smem_u32(smem);
    uint32_t sk = sq + 8192u;
    uint32_t sv = sq + 16384u;

    int t = threadIdx.x, wid = t >> 5, lane = t & 31;

    for (int i = t; i < 512; i += 128) {
        int row = i >> 3, c = i & 7;
        uint32_t off = (uint32_t)(row * 128 + c * 16);
        off ^= (off >> 3) & 0x70u;
        const size_t go = (size_t)row * KQKV + c * 8;
        cp16(sq + off, qb + go);
        cp16(sk + off, kb + go);
        cp16(sv + off, vb + go);
    }
    cp_commit();
    cp_wait<0>();
    __syncthreads();

    const int m0   = wid * 16;
    const int lrow = ((lane >> 3) & 1) * 8 + (lane & 7);
    const int lkb  = (lane >> 4) * 16;

    float sc[8][4];
    #pragma unroll
    for (int i = 0; i < 8; i++)
        #pragma unroll
        for (int e = 0; e < 4; e++) sc[i][e] = 0.0f;

    #pragma unroll
    for (int kk = 0; kk < 4; kk++) {
        int kbyte = kk * 32 + lkb;
        uint32_t aoff = (uint32_t)((m0 + lrow) * 128 + kbyte);
        aoff ^= (aoff >> 3) & 0x70u;
        uint32_t afr[4];
        ldsm4(afr, sq + aoff);
        #pragma unroll
        for (int nj = 0; nj < 4; nj++) {
            uint32_t boff = (uint32_t)((nj * 16 + lrow) * 128 + kbyte);
            boff ^= (boff >> 3) & 0x70u;
            uint32_t bfr[4];
            ldsm4(bfr, sk + boff);
            mma16816(sc[2 * nj],     afr, bfr[0], bfr[2]);
            mma16816(sc[2 * nj + 1], afr, bfr[1], bfr[3]);
        }
    }

    const float scale = 0.044194173824159216f;  // 1/sqrt(512)
    int r_lo = m0 + (lane >> 2);
    int r_hi = r_lo + 8;
    float mx0 = -1e30f, mx1 = -1e30f;
    #pragma unroll
    for (int nt = 0; nt < 8; nt++) {
        int c0 = nt * 8 + ((lane & 3) << 1);
        sc[nt][0] = (c0     <= r_lo) ? sc[nt][0] * scale : -1e30f;
        sc[nt][1] = (c0 + 1 <= r_lo) ? sc[nt][1] * scale : -1e30f;
        sc[nt][2] = (c0     <= r_hi) ? sc[nt][2] * scale : -1e30f;
        sc[nt][3] = (c0 + 1 <= r_hi) ? sc[nt][3] * scale : -1e30f;
        mx0 = fmaxf(mx0, fmaxf(sc[nt][0], sc[nt][1]));
        mx1 = fmaxf(mx1, fmaxf(sc[nt][2], sc[nt][3]));
    }
    mx0 = fmaxf(mx0, __shfl_xor_sync(0xffffffffu, mx0, 1));
    mx0 = fmaxf(mx0, __shfl_xor_sync(0xffffffffu, mx0, 2));
    mx1 = fmaxf(mx1, __shfl_xor_sync(0xffffffffu, mx1, 1));
    mx1 = fmaxf(mx1, __shfl_xor_sync(0xffffffffu, mx1, 2));

    float sum0 = 0.0f, sum1 = 0.0f;
    #pragma unroll
    for (int nt = 0; nt < 8; nt++) {
        sc[nt][0] = __expf(sc[nt][0] - mx0);
        sc[nt][1] = __expf(sc[nt][1] - mx0);
        sc[nt][2] = __expf(sc[nt][2] - mx1);
        sc[nt][3] = __expf(sc[nt][3] - mx1);
        sum0 += sc[nt][0] + sc[nt][1];
        sum1 += sc[nt][2] + sc[nt][3];
    }
    sum0 += __shfl_xor_sync(0xffffffffu, sum0, 1);
    sum0 += __shfl_xor_sync(0xffffffffu, sum0, 2);
    sum1 += __shfl_xor_sync(0xffffffffu, sum1, 1);
    sum1 += __shfl_xor_sync(0xffffffffu, sum1, 2);
    float inv0 = 1.0f / sum0, inv1 = 1.0f / sum1;

    float oacc[8][4];
    #pragma unroll
    for (int i = 0; i < 8; i++)
        #pragma unroll
        for (int e = 0; e < 4; e++) oacc[i][e] = 0.0f;

    int jrow = lane & 15;
    int echunk = (lane >> 4) * 16;
    #pragma unroll
    for (int kk = 0; kk < 4; kk++) {
        uint32_t afr[4];
        afr[0] = pack_h2(sc[2 * kk][0] * inv0,     sc[2 * kk][1] * inv0);
        afr[1] = pack_h2(sc[2 * kk][2] * inv1,     sc[2 * kk][3] * inv1);
        afr[2] = pack_h2(sc[2 * kk + 1][0] * inv0, sc[2 * kk + 1][1] * inv0);
        afr[3] = pack_h2(sc[2 * kk + 1][2] * inv1, sc[2 * kk + 1][3] * inv1);

        #pragma unroll
        for (int ne = 0; ne < 4; ne++) {
            uint32_t boff = (uint32_t)((kk * 16 + jrow) * 128 + ne * 32 + echunk);
            boff ^= (boff >> 3) & 0x70u;
            uint32_t bfr[4];
            ldsm4t(bfr, sv + boff);
            mma16816(oacc[2 * ne],     afr, bfr[0], bfr[1]);
            mma16816(oacc[2 * ne + 1], afr, bfr[2], bfr[3]);
        }
    }

    #pragma unroll
    for (int nt = 0; nt < 8; nt++) {
        int e = nt * 8 + ((lane & 3) << 1);
        *(uint32_t*)&ob[(size_t)r_lo * DD + e] = pack_h2(oacc[nt][0], oacc[nt][1]);
        *(uint32_t*)&ob[(size_t)r_hi * DD + e] = pack_h2(oacc[nt][2], oacc[nt][3]);
    }
}

// ---------------- fused unembed + cross-entropy loss ------------------------
#define UROWS 16
__global__ void __launch_bounds__(128) unembed_loss_kernel(
    const float* __restrict__ x, const float* __restrict__ Wu,
    const float* __restrict__ bu, const int* __restrict__ tgt,
    float* __restrict__ logits)
{
    __shared__ float xs[UROWS][DD];
    __shared__ float lgs[UROWS][VV + 2];
    int r0 = blockIdx.x * UROWS;
    const float4* src = (const float4*)(x + (size_t)r0 * DD);
    float4* dst = (float4*)&xs[0][0];
    for (int i = threadIdx.x; i < UROWS * DD / 4; i += 128)
        dst[i] = src[i];
    __syncthreads();
    int c = threadIdx.x;
    if (c < VV) {
        float acc[UROWS];
        float bc = bu[c];
        #pragma unroll
        for (int r = 0; r < UROWS; r++) acc[r] = bc;
        #pragma unroll 4
        for (int k = 0; k < DD; k++) {
            float w = Wu[(size_t)k * VV + c];
            #pragma unroll
            for (int r = 0; r < UROWS; r++)
                acc[r] = fmaf(xs[r][k], w, acc[r]);
        }
        #pragma unroll
        for (int r = 0; r < UROWS; r++) {
            logits[(size_t)(r0 + r) * VV + c] = acc[r];
            lgs[r][c] = acc[r];
        }
    }
    __syncthreads();

    int wid = threadIdx.x >> 5, lane = threadIdx.x & 31;
    float part = 0.0f;
    #pragma unroll
    for (int rr = 0; rr < 4; rr++) {
        int r = wid * 4 + rr;
        float l0 = lgs[r][lane];
        float l1 = lgs[r][lane + 32];
        float l2 = (lane + 64 < VV) ? lgs[r][lane + 64] : -1e30f;
        float m = fmaxf(fmaxf(l0, l1), l2);
        #pragma unroll
        for (int off = 16; off; off >>= 1)
            m = fmaxf(m, __shfl_xor_sync(0xffffffffu, m, off));
        float sum = expf(l0 - m) + expf(l1 - m) +
                    ((lane + 64 < VV) ? expf(l2 - m) : 0.0f);
        #pragma unroll
        for (int off = 16; off; off >>= 1)
            sum += __shfl_xor_sync(0xffffffffu, sum, off);
        if (lane == 0)
            part += (m + logf(sum)) - lgs[r][tgt[r0 + r]];
    }
    if (lane == 0) atomicAdd(&g_loss, part);
}

// ---------------- output assembly -------------------------------------------
__global__ void __launch_bounds__(256) copy_out_kernel(
    const float* __restrict__ lg, float* __restrict__ out, int n)
{
    int i = blockIdx.x * 256 + threadIdx.x;
    if (i < n) out[i] = lg[i];
}
__global__ void __launch_bounds__(128) write_loss_kernel(
    float* __restrict__ out, int lo, int hi)
{
    int i = lo + blockIdx.x * 128 + threadIdx.x;
    if (i < hi) out[i] = g_loss * (1.0f / (float)MM);
}

// ---------------- launcher ----------------------------------------------------
extern "C" void kernel_launch(void* const* d_in, const int* in_sizes, int n_in,
                              void* d_out, int out_size)
{
    const int*   ids  = (const int*)d_in[0];
    const int*   tgt  = (const int*)d_in[1];
    const float* tok  = (const float*)d_in[2];
    const float* pos  = (const float*)d_in[3];
    const float* Wq   = (const float*)d_in[4];
    const float* Wk   = (const float*)d_in[5];
    const float* Wv   = (const float*)d_in[6];
    const float* Wo   = (const float*)d_in[7];
    const float* bo   = (const float*)d_in[8];
    const float* W1   = (const float*)d_in[9];
    const float* b1   = (const float*)d_in[10];
    const float* W2   = (const float*)d_in[11];
    const float* b2   = (const float*)d_in[12];
    const float* ln1g = (const float*)d_in[13];
    const float* ln1b = (const float*)d_in[14];
    const float* ln2g = (const float*)d_in[15];
    const float* ln2b = (const float*)d_in[16];
    const float* lnfg = (const float*)d_in[17];
    const float* lnfb = (const float*)d_in[18];
    const float* Wu   = (const float*)d_in[19];
    const float* bu   = (const float*)d_in[20];
    float* out = (float*)d_out;

    float *x, *h, *lg;
    __half *qkv, *hA1, *oA, *hidA, *Wqkv, *WoT, *W1T, *W2T;
    cudaGetSymbolAddress((void**)&x,    g_x);
    cudaGetSymbolAddress((void**)&h,    g_h);
    cudaGetSymbolAddress((void**)&qkv,  g_qkv);
    cudaGetSymbolAddress((void**)&hA1,  g_hA1);
    cudaGetSymbolAddress((void**)&oA,   g_oA);
    cudaGetSymbolAddress((void**)&hidA, g_hidA);
    cudaGetSymbolAddress((void**)&lg,   g_logits);
    cudaGetSymbolAddress((void**)&Wqkv, g_Wqkv);
    cudaGetSymbolAddress((void**)&WoT,  g_WoT);
    cudaGetSymbolAddress((void**)&W1T,  g_W1T);
    cudaGetSymbolAddress((void**)&W2T,  g_W2T);

    cudaFuncSetAttribute(gemm_mma<0>, cudaFuncAttributeMaxDynamicSharedMemorySize, GSMEM);
    cudaFuncSetAttribute(gemm_mma<1>, cudaFuncAttributeMaxDynamicSharedMemorySize, GSMEM);
    cudaFuncSetAttribute(gemm_mma<2>, cudaFuncAttributeMaxDynamicSharedMemorySize, GSMEM);

    int nlog = MM * VV;
    float* logits_dst = (out_size >= nlog) ? out : lg;

    // ---- weight prep: 3 launches (grid.z = layer[*part]) ----
    dim3 pb(32, 8);
    prep_w_qkvo<<<dim3(DD/32, DD/32, 4*LL), pb>>>(Wq, Wk, Wv, Wo, Wqkv, WoT);
    prep_w_single<<<dim3(DD/32, DFF/32, LL), pb>>>(W1, DD, DFF,
        W1T,  (size_t)DFF * DD);
    prep_w_single<<<dim3(DFF/32, DD/32, LL), pb>>>(W2, DFF, DD,
        W2T,  (size_t)DD * DFF);

    embed_kernel<<<(MM * DD + 255) / 256, 256>>>(ids, tok, pos, x);

    for (int l = 0; l < LL; l++) {
        ln_single_kernel<<<MM / 8, 256>>>(x, ln1g + l * DD, ln1b + l * DD, hA1);

        // qkv(fp16) = hA1 @ Wqkv^T   K=512
        gemm_mma<0><<<dim3(KQKV/128, MM/128), 128, GSMEM>>>(
            hA1, DD, Wqkv + (size_t)l*KQKV*DD, DD, DD,
            nullptr, qkv, KQKV, nullptr, nullptr);

        attn_mma_kernel<<<BB * HH, 128>>>(qkv, oA);

        // x = x + o @ Wo + bo    K=512
        gemm_mma<1><<<dim3(DD/128, MM/128), 128, GSMEM>>>(
            oA, DD, WoT + (size_t)l*DD*DD, DD, DD,
            x, nullptr, DD, bo + l * DD, x);

        ln_single_kernel<<<MM / 8, 256>>>(x, ln2g + l * DD, ln2b + l * DD, hA1);

        // hidA(fp16) = gelu(hA1 @ W1^T + b1)   K=512
        gemm_mma<2><<<dim3(DFF/128, MM/128), 128, GSMEM>>>(
            hA1, DD, W1T + (size_t)l*DFF*DD, DD, DD,
            nullptr, hidA, DFF, b1 + l * DFF, nullptr);

        // x = x + hid @ W2 + b2   K=2048
        gemm_mma<1><<<dim3(DD/128, MM/128), 128, GSMEM>>>(
            hidA, DFF, W2T + (size_t)l*DD*DFF, DFF, DFF,
            x, nullptr, DD, b2 + l * DD, x);
    }

    ln_kernel<<<MM / 8, 256>>>(x, lnfg, lnfb, h);
    unembed_loss_kernel<<<MM / UROWS, 128>>>(h, Wu, bu, tgt, logits_dst);

    if (logits_dst != out) {
        int ncopy = out_size < nlog ? out_size : nlog;
        if (ncopy > 0)
            copy_out_kernel<<<(ncopy + 255) / 256, 256>>>(lg, out, ncopy);
    }
    if (out_size > nlog) {
        int tail = out_size - nlog;
        write_loss_kernel<<<(tail + 127) / 128, 128>>>(out, nlog, out_size);
    }
}